// round 8
// baseline (speedup 1.0000x reference)
#include <cuda_runtime.h>
#include <math.h>

#define Hh 512
#define Bb 64
#define Ss 512
#define Ii 128
#define G4 2048

// ---------------- device-global scratch (no allocations allowed) ----------------
__device__ float g_act[Ss * Bb * Hh];   // (S,B,H): quantum out q, then hs per layer
__device__ float g_xp[Ss * G4 * Bb];    // (S, 4H, B) x-projection, TRANSPOSED for lstm reads
__device__ float g_cw[Ii * Hh];         // cos(theta+noise), layout (I,H)
__device__ float g_sw[Ii * Hh];         // sin(phi+noise),   layout (I,H)
__device__ float g_fc1[Bb * Hh];
__device__ unsigned g_cnt;
__device__ volatile unsigned g_gen;

// ---------------- grid barrier (persistent kernel, 128 co-resident CTAs) --------
__device__ __forceinline__ void gbar(unsigned nb) {
    __threadfence();
    __syncthreads();
    if (threadIdx.x == 0) {
        unsigned gen = g_gen;
        if (atomicAdd(&g_cnt, 1u) == nb - 1u) {
            g_cnt = 0u;
            __threadfence();
            g_gen = gen + 1u;
        } else {
            while (g_gen == gen) { __nanosleep(64); }
            __threadfence();
        }
    }
    __syncthreads();
}

// ---------------- tf32 helpers ----------------
__device__ __forceinline__ unsigned f2tf32(float x) {
    unsigned u;
    asm("cvt.rna.tf32.f32 %0, %1;" : "=r"(u) : "f"(x));
    return u;
}
__device__ __forceinline__ float2 split_tf32(float x) {
    float hi = __uint_as_float(f2tf32(x));
    return make_float2(hi, x - hi);
}
__device__ __forceinline__ void mma_tf32(float c[4],
                                         unsigned a0, unsigned a1, unsigned a2, unsigned a3,
                                         unsigned b0, unsigned b1) {
    asm volatile(
        "mma.sync.aligned.m16n8k8.row.col.f32.tf32.tf32.f32 "
        "{%0,%1,%2,%3},{%4,%5,%6,%7},{%8,%9},{%0,%1,%2,%3};\n"
        : "+f"(c[0]), "+f"(c[1]), "+f"(c[2]), "+f"(c[3])
        : "r"(a0), "r"(a1), "r"(a2), "r"(a3), "r"(b0), "r"(b1));
}

// ---------------- trig precompute ----------------
__global__ void k_trig(const float* __restrict__ th, const float* __restrict__ ph,
                       const float* __restrict__ tn, const float* __restrict__ pn) {
    int i = blockIdx.x * 256 + threadIdx.x;
    if (i < Ii * Hh) {
        g_cw[i] = cosf(th[i] + tn[i]);
        g_sw[i] = sinf(ph[i] + pn[i]);
    }
}

// ---------------- quantum layer: q[s][b][h] = sqrt(real^2 + imag^2) -------------
__global__ void __launch_bounds__(256) k_quant(const float* __restrict__ x) {
    __shared__ float As[16][68], Cs[16][68], Sm[16][68];
    int m0 = blockIdx.x * 64, n0 = blockIdx.y * 64;
    int tid = threadIdx.x;
    int tx = tid & 15, ty = tid >> 4;
    float aR[4][4] = {}, aI[4][4] = {};

    for (int kc = 0; kc < Ii; kc += 16) {
        {
            int ml = tid >> 2, k4 = tid & 3;
            float4 v = *(const float4*)(x + (size_t)(m0 + ml) * Ii + kc + k4 * 4);
            As[k4 * 4 + 0][ml] = v.x; As[k4 * 4 + 1][ml] = v.y;
            As[k4 * 4 + 2][ml] = v.z; As[k4 * 4 + 3][ml] = v.w;
        }
        {
            int k = tid >> 4, n4 = tid & 15;
            float4 c = *(const float4*)(g_cw + (size_t)(kc + k) * Hh + n0 + n4 * 4);
            float4 s = *(const float4*)(g_sw + (size_t)(kc + k) * Hh + n0 + n4 * 4);
            *(float4*)&Cs[k][n4 * 4] = c;
            *(float4*)&Sm[k][n4 * 4] = s;
        }
        __syncthreads();
        #pragma unroll
        for (int k = 0; k < 16; k++) {
            float4 a  = *(const float4*)&As[k][ty * 4];
            float4 bc = *(const float4*)&Cs[k][tx * 4];
            float4 bs = *(const float4*)&Sm[k][tx * 4];
            float av[4] = {a.x, a.y, a.z, a.w};
            float cv[4] = {bc.x, bc.y, bc.z, bc.w};
            float sv[4] = {bs.x, bs.y, bs.z, bs.w};
            #pragma unroll
            for (int i = 0; i < 4; i++) {
                #pragma unroll
                for (int j = 0; j < 4; j++) {
                    aR[i][j] += av[i] * cv[j];
                    aI[i][j] += av[i] * sv[j];
                }
            }
        }
        __syncthreads();
    }
    #pragma unroll
    for (int i = 0; i < 4; i++) {
        int m = m0 + ty * 4 + i;
        int b = m >> 9, s = m & 511;
        float4 o;
        o.x = sqrtf(aR[i][0] * aR[i][0] + aI[i][0] * aI[i][0]);
        o.y = sqrtf(aR[i][1] * aR[i][1] + aI[i][1] * aI[i][1]);
        o.z = sqrtf(aR[i][2] * aR[i][2] + aI[i][2] * aI[i][2]);
        o.w = sqrtf(aR[i][3] * aR[i][3] + aI[i][3] * aI[i][3]);
        *(float4*)(g_act + (size_t)s * (Bb * Hh) + (size_t)b * Hh + n0 + tx * 4) = o;
    }
}

// ---------------- x-projection (tensor cores, split tf32 3-mma) -----------------
// C[m][n] = act[m] . W[n], m=0..32767 (m=s*64+b), n=0..2047, K=512.
// Output written TRANSPOSED: g_xp[s*131072 + n*64 + b]  (+ bi[n] + bh[n]).
// Block 128x128, BK=16, 8 warps (warp grid 2m x 4n), warp tile 64x32.
#define PIT 132   // float2 pitch: 132 mod 16 == 4 -> 2-way max bank degree on frags

__global__ void __launch_bounds__(256, 1) k_xproj(const float* __restrict__ W,
                                                  const float* __restrict__ bi,
                                                  const float* __restrict__ bh,
                                                  float* __restrict__ xpo) {
    __shared__ float2 As2[16 * PIT];   // [k][m] hi/lo
    __shared__ float2 Bs2[16 * PIT];   // [k][n] hi/lo
    __shared__ float bsum[128];

    const int tid = threadIdx.x;
    const int m0 = blockIdx.x * 128;
    const int n0 = blockIdx.y * 128;
    const int lane = tid & 31, warp = tid >> 5;
    const int wm0 = (warp >> 2) * 64;
    const int wn0 = (warp & 3) * 32;
    const int g = lane >> 2, t = lane & 3;

    if (tid < 128) bsum[tid] = bi[n0 + tid] + bh[n0 + tid];

    const int srow = tid >> 1;
    const int sks  = (tid & 1) * 8;
    const float* gA = g_act + (size_t)(m0 + srow) * Hh + sks;
    const float* gB = W + (size_t)(n0 + srow) * Hh + sks;

    float4 ra0 = *(const float4*)(gA);
    float4 ra1 = *(const float4*)(gA + 4);
    float4 rb0 = *(const float4*)(gB);
    float4 rb1 = *(const float4*)(gB + 4);

    float acc[4][4][4];
    #pragma unroll
    for (int i = 0; i < 4; i++)
        #pragma unroll
        for (int j = 0; j < 4; j++)
            #pragma unroll
            for (int r = 0; r < 4; r++) acc[i][j][r] = 0.0f;

    for (int it = 0; it < 32; ++it) {
        {   // stage current tile (hi/lo split at store time)
            float av[8] = {ra0.x, ra0.y, ra0.z, ra0.w, ra1.x, ra1.y, ra1.z, ra1.w};
            float bv[8] = {rb0.x, rb0.y, rb0.z, rb0.w, rb1.x, rb1.y, rb1.z, rb1.w};
            #pragma unroll
            for (int j = 0; j < 8; j++) {
                As2[(sks + j) * PIT + srow] = split_tf32(av[j]);
                Bs2[(sks + j) * PIT + srow] = split_tf32(bv[j]);
            }
        }
        __syncthreads();
        if (it < 31) {   // prefetch next tile (latency hidden under compute)
            gA += 16; gB += 16;
            ra0 = *(const float4*)(gA);
            ra1 = *(const float4*)(gA + 4);
            rb0 = *(const float4*)(gB);
            rb1 = *(const float4*)(gB + 4);
        }
        #pragma unroll
        for (int ko = 0; ko < 16; ko += 8) {
            float2 Af[4][4];
            #pragma unroll
            for (int mt = 0; mt < 4; mt++) {
                int r0 = wm0 + mt * 16 + g;
                Af[mt][0] = As2[(ko + t) * PIT + r0];
                Af[mt][1] = As2[(ko + t) * PIT + r0 + 8];
                Af[mt][2] = As2[(ko + t + 4) * PIT + r0];
                Af[mt][3] = As2[(ko + t + 4) * PIT + r0 + 8];
            }
            float2 Bf[4][2];
            #pragma unroll
            for (int nt = 0; nt < 4; nt++) {
                int n = wn0 + nt * 8 + g;
                Bf[nt][0] = Bs2[(ko + t) * PIT + n];
                Bf[nt][1] = Bs2[(ko + t + 4) * PIT + n];
            }
            #pragma unroll
            for (int mt = 0; mt < 4; mt++) {
                unsigned ah0 = __float_as_uint(Af[mt][0].x), ah1 = __float_as_uint(Af[mt][1].x);
                unsigned ah2 = __float_as_uint(Af[mt][2].x), ah3 = __float_as_uint(Af[mt][3].x);
                unsigned al0 = f2tf32(Af[mt][0].y), al1 = f2tf32(Af[mt][1].y);
                unsigned al2 = f2tf32(Af[mt][2].y), al3 = f2tf32(Af[mt][3].y);
                #pragma unroll
                for (int nt = 0; nt < 4; nt++) {
                    unsigned bh0 = __float_as_uint(Bf[nt][0].x);
                    unsigned bh1 = __float_as_uint(Bf[nt][1].x);
                    unsigned bl0 = f2tf32(Bf[nt][0].y);
                    unsigned bl1 = f2tf32(Bf[nt][1].y);
                    mma_tf32(acc[mt][nt], ah0, ah1, ah2, ah3, bh0, bh1);  // hi*hi
                    mma_tf32(acc[mt][nt], ah0, ah1, ah2, ah3, bl0, bl1);  // hi*lo
                    mma_tf32(acc[mt][nt], al0, al1, al2, al3, bh0, bh1);  // lo*hi
                }
            }
        }
        __syncthreads();
    }

    // epilogue: C layout c0:(g,2t) c1:(g,2t+1) c2:(g+8,2t) c3:(g+8,2t+1)
    #pragma unroll
    for (int mt = 0; mt < 4; mt++) {
        int r0g = m0 + wm0 + mt * 16 + g;          // rows r0g, r0g+8
        int s0 = r0g >> 6, b0 = r0g & 63;
        int s1 = (r0g + 8) >> 6, b1 = (r0g + 8) & 63;
        #pragma unroll
        for (int nt = 0; nt < 4; nt++) {
            int col = wn0 + nt * 8 + 2 * t;        // local n, n+1
            float bs0 = bsum[col], bs1 = bsum[col + 1];
            size_t i00 = (size_t)s0 * 131072 + (size_t)(n0 + col) * 64 + b0;
            size_t i10 = (size_t)s1 * 131072 + (size_t)(n0 + col) * 64 + b1;
            xpo[i00]      = acc[mt][nt][0] + bs0;
            xpo[i00 + 64] = acc[mt][nt][1] + bs1;
            xpo[i10]      = acc[mt][nt][2] + bs0;
            xpo[i10 + 64] = acc[mt][nt][3] + bs1;
        }
    }
}

// ---------------- persistent LSTM recurrence (one launch per layer) -------------
#define PITCH 516
#define HOFF  (16 * PITCH)
#define POFF  (HOFF + 64 * PITCH)
#define LSTM_SMEM ((POFF + 4096) * 4)

__global__ void __launch_bounds__(256) k_lstm(const float* __restrict__ Whh,
                                              const float* __restrict__ xp,
                                              float* __restrict__ hs) {
    extern __shared__ float sm[];
    const int tid = threadIdx.x;
    const int u0  = blockIdx.x * 4;

    for (int i4 = tid; i4 < 2048; i4 += 256) {
        int r = i4 >> 7, k4 = i4 & 127;
        int g = r >> 2, u = r & 3;
        float4 v = *(const float4*)(Whh + (size_t)(g * Hh + u0 + u) * Hh + k4 * 4);
        *(float4*)&sm[r * PITCH + k4 * 4] = v;
    }

    const int kq = tid >> 6;
    const int rg = (tid >> 4) & 3;
    const int bg = tid & 15;
    const int eu = tid & 3;
    const int eb = tid >> 2;

    float c_reg = 0.0f;

    for (int s = 0; s < Ss; s++) {
        if (s > 0) {
            const float* hp = hs + (size_t)(s - 1) * (Bb * Hh);
            for (int i4 = tid; i4 < 8192; i4 += 256) {
                int b = i4 >> 7, k4 = i4 & 127;
                *(float4*)&sm[HOFF + b * PITCH + k4 * 4] =
                    *(const float4*)(hp + (size_t)b * Hh + k4 * 4);
            }
        }
        __syncthreads();

        if (s > 0) {
            float acc[4][4] = {};
            const float* wp = sm + (rg * 4) * PITCH + kq * 128;
            const float* hq = sm + HOFF + bg * PITCH + kq * 128;
            #pragma unroll 4
            for (int k = 0; k < 128; k += 4) {
                float4 wv[4], hv[4];
                #pragma unroll
                for (int i = 0; i < 4; i++) wv[i] = *(const float4*)(wp + i * PITCH + k);
                #pragma unroll
                for (int b = 0; b < 4; b++) hv[b] = *(const float4*)(hq + b * 16 * PITCH + k);
                #pragma unroll
                for (int i = 0; i < 4; i++) {
                    #pragma unroll
                    for (int b = 0; b < 4; b++) {
                        acc[i][b] += wv[i].x * hv[b].x + wv[i].y * hv[b].y
                                   + wv[i].z * hv[b].z + wv[i].w * hv[b].w;
                    }
                }
            }
            #pragma unroll
            for (int i = 0; i < 4; i++) {
                #pragma unroll
                for (int b = 0; b < 4; b++) {
                    int out = (rg * 4 + i) * 64 + (bg + b * 16);
                    sm[POFF + out * 4 + kq] = acc[i][b];
                }
            }
        }
        __syncthreads();

        {   // xp layout: (s, n, b) with n = g*512 + (u0+eu) -> coalesced reads
            const float* xr = xp + (size_t)s * (G4 * Bb) + (size_t)(u0 + eu) * 64 + eb;
            float gate[4];
            #pragma unroll
            for (int g = 0; g < 4; g++) {
                float v = xr[(size_t)g * (Hh * Bb)];
                if (s > 0) {
                    int out = (g * 4 + eu) * 64 + eb;
                    v += sm[POFF + out * 4 + 0] + sm[POFF + out * 4 + 1]
                       + sm[POFF + out * 4 + 2] + sm[POFF + out * 4 + 3];
                }
                gate[g] = v;
            }
            float ig = 1.0f / (1.0f + expf(-gate[0]));
            float fg = 1.0f / (1.0f + expf(-gate[1]));
            float gg = tanhf(gate[2]);
            float og = 1.0f / (1.0f + expf(-gate[3]));
            c_reg = (s == 0) ? (ig * gg) : (fg * c_reg + ig * gg);
            float hv = og * tanhf(c_reg);
            hs[(size_t)s * (Bb * Hh) + (size_t)eb * Hh + u0 + eu] = hv;
        }
        gbar(gridDim.x);
    }
}

// ---------------- FC head ----------------
__global__ void k_fc1(const float* __restrict__ w, const float* __restrict__ bias) {
    int t = blockIdx.x * 256 + threadIdx.x;
    int j = t >> 6, b = t & 63;
    const float* lr = g_act + (size_t)511 * (Bb * Hh) + (size_t)b * Hh;
    const float* wr = w + (size_t)j * Hh;
    float a = 0.0f;
    for (int k = 0; k < Hh; k += 4) {
        float4 wv = *(const float4*)(wr + k);
        float4 lv = *(const float4*)(lr + k);
        a += wv.x * lv.x + wv.y * lv.y + wv.z * lv.z + wv.w * lv.w;
    }
    a += bias[j];
    g_fc1[b * Hh + j] = fmaxf(a, 0.0f);
}

__global__ void k_fc2(const float* __restrict__ w, const float* __restrict__ bias,
                      float* __restrict__ out) {
    __shared__ float red[128];
    int b = blockIdx.x, tid = threadIdx.x;
    float a = 0.0f;
    for (int j = tid; j < Hh; j += 128) a += g_fc1[b * Hh + j] * w[j];
    red[tid] = a;
    __syncthreads();
    for (int s2 = 64; s2 > 0; s2 >>= 1) {
        if (tid < s2) red[tid] += red[tid + s2];
        __syncthreads();
    }
    if (tid == 0) out[b] = red[0] + bias[0];
}

// ---------------- launch ----------------
extern "C" void kernel_launch(void* const* d_in, const int* in_sizes, int n_in,
                              void* d_out, int out_size) {
    const float* x   = (const float*)d_in[0];
    const float* th  = (const float*)d_in[1];
    const float* ph  = (const float*)d_in[2];
    const float* tn  = (const float*)d_in[3];
    const float* pn  = (const float*)d_in[4];
    const float* Wih = (const float*)d_in[5];
    const float* Whh = (const float*)d_in[6];
    const float* bih = (const float*)d_in[7];
    const float* bhh = (const float*)d_in[8];
    const float* f1w = (const float*)d_in[9];
    const float* f1b = (const float*)d_in[10];
    const float* f2w = (const float*)d_in[11];
    const float* f2b = (const float*)d_in[12];
    float* out = (float*)d_out;

    cudaFuncSetAttribute(k_lstm, cudaFuncAttributeMaxDynamicSharedMemorySize, LSTM_SMEM);

    float* xp_ptr  = nullptr;
    float* act_ptr = nullptr;
    cudaGetSymbolAddress((void**)&xp_ptr, g_xp);
    cudaGetSymbolAddress((void**)&act_ptr, g_act);

    k_trig<<<256, 256>>>(th, ph, tn, pn);
    k_quant<<<dim3(512, 8), 256>>>(x);

    for (int l = 0; l < 2; l++) {
        k_xproj<<<dim3(256, 16), 256>>>(Wih + (size_t)l * G4 * Hh,
                                        bih + (size_t)l * G4,
                                        bhh + (size_t)l * G4,
                                        xp_ptr);
        k_lstm<<<128, 256, LSTM_SMEM>>>(Whh + (size_t)l * G4 * Hh, xp_ptr, act_ptr);
    }

    k_fc1<<<128, 256>>>(f1w, f1b);
    k_fc2<<<64, 128>>>(f2w, f2b, out);
}

// round 9
// speedup vs baseline: 1.0033x; 1.0033x over previous
#include <cuda_runtime.h>
#include <math.h>

#define Hh 512
#define Bb 64
#define Ss 512
#define Ii 128
#define G4 2048

// ---------------- device-global scratch (no allocations allowed) ----------------
__device__ float g_act[Ss * Bb * Hh];   // (S,B,H): quantum out q, then hs per layer
__device__ float g_xp[Ss * G4 * Bb];    // (S, 4H, B) x-projection, TRANSPOSED for lstm reads
__device__ float g_cw[Ii * Hh];         // cos(theta+noise), layout (I,H)
__device__ float g_sw[Ii * Hh];         // sin(phi+noise),   layout (I,H)
__device__ float g_fc1[Bb * Hh];
__device__ unsigned g_cnt;
__device__ volatile unsigned g_gen;

// ---------------- grid barrier (persistent kernel, 128 co-resident CTAs) --------
__device__ __forceinline__ void gbar(unsigned nb) {
    __threadfence();
    __syncthreads();
    if (threadIdx.x == 0) {
        unsigned gen = g_gen;
        if (atomicAdd(&g_cnt, 1u) == nb - 1u) {
            g_cnt = 0u;
            __threadfence();
            g_gen = gen + 1u;
        } else {
            while (g_gen == gen) { __nanosleep(32); }
            __threadfence();
        }
    }
    __syncthreads();
}

// ---------------- tf32 helpers ----------------
__device__ __forceinline__ unsigned f2tf32(float x) {
    unsigned u;
    asm("cvt.rna.tf32.f32 %0, %1;" : "=r"(u) : "f"(x));
    return u;
}
// hi and lo BOTH stored as tf32-rounded bit patterns -> no cvt in mma loop
__device__ __forceinline__ float2 split2(float x) {
    float hi = __uint_as_float(f2tf32(x));
    float lo = __uint_as_float(f2tf32(x - hi));
    return make_float2(hi, lo);
}
__device__ __forceinline__ void mma_tf32(float c[4],
                                         unsigned a0, unsigned a1, unsigned a2, unsigned a3,
                                         unsigned b0, unsigned b1) {
    asm volatile(
        "mma.sync.aligned.m16n8k8.row.col.f32.tf32.tf32.f32 "
        "{%0,%1,%2,%3},{%4,%5,%6,%7},{%8,%9},{%0,%1,%2,%3};\n"
        : "+f"(c[0]), "+f"(c[1]), "+f"(c[2]), "+f"(c[3])
        : "r"(a0), "r"(a1), "r"(a2), "r"(a3), "r"(b0), "r"(b1));
}

// ---------------- trig precompute ----------------
__global__ void k_trig(const float* __restrict__ th, const float* __restrict__ ph,
                       const float* __restrict__ tn, const float* __restrict__ pn) {
    int i = blockIdx.x * 256 + threadIdx.x;
    if (i < Ii * Hh) {
        g_cw[i] = cosf(th[i] + tn[i]);
        g_sw[i] = sinf(ph[i] + pn[i]);
    }
}

// ---------------- quantum layer: q[s][b][h] = sqrt(real^2 + imag^2) -------------
__global__ void __launch_bounds__(256) k_quant(const float* __restrict__ x) {
    __shared__ float As[16][68], Cs[16][68], Sm[16][68];
    int m0 = blockIdx.x * 64, n0 = blockIdx.y * 64;
    int tid = threadIdx.x;
    int tx = tid & 15, ty = tid >> 4;
    float aR[4][4] = {}, aI[4][4] = {};

    for (int kc = 0; kc < Ii; kc += 16) {
        {
            int ml = tid >> 2, k4 = tid & 3;
            float4 v = *(const float4*)(x + (size_t)(m0 + ml) * Ii + kc + k4 * 4);
            As[k4 * 4 + 0][ml] = v.x; As[k4 * 4 + 1][ml] = v.y;
            As[k4 * 4 + 2][ml] = v.z; As[k4 * 4 + 3][ml] = v.w;
        }
        {
            int k = tid >> 4, n4 = tid & 15;
            float4 c = *(const float4*)(g_cw + (size_t)(kc + k) * Hh + n0 + n4 * 4);
            float4 s = *(const float4*)(g_sw + (size_t)(kc + k) * Hh + n0 + n4 * 4);
            *(float4*)&Cs[k][n4 * 4] = c;
            *(float4*)&Sm[k][n4 * 4] = s;
        }
        __syncthreads();
        #pragma unroll
        for (int k = 0; k < 16; k++) {
            float4 a  = *(const float4*)&As[k][ty * 4];
            float4 bc = *(const float4*)&Cs[k][tx * 4];
            float4 bs = *(const float4*)&Sm[k][tx * 4];
            float av[4] = {a.x, a.y, a.z, a.w};
            float cv[4] = {bc.x, bc.y, bc.z, bc.w};
            float sv[4] = {bs.x, bs.y, bs.z, bs.w};
            #pragma unroll
            for (int i = 0; i < 4; i++) {
                #pragma unroll
                for (int j = 0; j < 4; j++) {
                    aR[i][j] += av[i] * cv[j];
                    aI[i][j] += av[i] * sv[j];
                }
            }
        }
        __syncthreads();
    }
    #pragma unroll
    for (int i = 0; i < 4; i++) {
        int m = m0 + ty * 4 + i;
        int b = m >> 9, s = m & 511;
        float4 o;
        o.x = sqrtf(aR[i][0] * aR[i][0] + aI[i][0] * aI[i][0]);
        o.y = sqrtf(aR[i][1] * aR[i][1] + aI[i][1] * aI[i][1]);
        o.z = sqrtf(aR[i][2] * aR[i][2] + aI[i][2] * aI[i][2]);
        o.w = sqrtf(aR[i][3] * aR[i][3] + aI[i][3] * aI[i][3]);
        *(float4*)(g_act + (size_t)s * (Bb * Hh) + (size_t)b * Hh + n0 + tx * 4) = o;
    }
}

// ---------------- x-projection (tensor cores, split tf32 3-mma, dbl-buffered) ---
// C[m][n] = act[m] . W[n], m=s*64+b in 0..32767, n in 0..2047, K=512.
// Output TRANSPOSED: g_xp[s*131072 + n*64 + b] (+bi[n]+bh[n]).
// Block 128x128, BK=16, 8 warps (2m x 4n), warp tile 64x32.
// Dyn smem: 2 buffers x (A[16*PIT] + B[16*PIT]) float2(hi,lo), both tf32-rounded.
#define PIT 132
#define XBUF (32 * PIT)                 // float2 per buffer (A then B)
#define XSMEM (2 * XBUF * 8)            // bytes = 67584

__global__ void __launch_bounds__(256, 1) k_xproj(const float* __restrict__ W,
                                                  const float* __restrict__ bi,
                                                  const float* __restrict__ bh,
                                                  float* __restrict__ xpo) {
    extern __shared__ float2 dyn[];
    __shared__ float bsum[128];

    const int tid = threadIdx.x;
    const int m0 = blockIdx.x * 128;
    const int n0 = blockIdx.y * 128;
    const int lane = tid & 31, warp = tid >> 5;
    const int wm0 = (warp >> 2) * 64;
    const int wn0 = (warp & 3) * 32;
    const int g = lane >> 2, t = lane & 3;

    if (tid < 128) bsum[tid] = bi[n0 + tid] + bh[n0 + tid];

    const int srow = tid >> 1;
    const int sks  = (tid & 1) * 8;
    const float* gA = g_act + (size_t)(m0 + srow) * Hh + sks;
    const float* gB = W + (size_t)(n0 + srow) * Hh + sks;

    float4 ra0 = *(const float4*)(gA);
    float4 ra1 = *(const float4*)(gA + 4);
    float4 rb0 = *(const float4*)(gB);
    float4 rb1 = *(const float4*)(gB + 4);

    float acc[4][4][4];
    #pragma unroll
    for (int i = 0; i < 4; i++)
        #pragma unroll
        for (int j = 0; j < 4; j++)
            #pragma unroll
            for (int r = 0; r < 4; r++) acc[i][j][r] = 0.0f;

    // stage tile 0 into buffer 0
    {
        float av[8] = {ra0.x, ra0.y, ra0.z, ra0.w, ra1.x, ra1.y, ra1.z, ra1.w};
        float bv[8] = {rb0.x, rb0.y, rb0.z, rb0.w, rb1.x, rb1.y, rb1.z, rb1.w};
        #pragma unroll
        for (int j = 0; j < 8; j++) {
            dyn[(sks + j) * PIT + srow] = split2(av[j]);
            dyn[16 * PIT + (sks + j) * PIT + srow] = split2(bv[j]);
        }
    }
    __syncthreads();

    for (int it = 0; it < 32; ++it) {
        const float2* Ab = dyn + (it & 1) * XBUF;
        const float2* Bbuf = Ab + 16 * PIT;

        if (it < 31) {   // issue next tile's global loads before compute
            gA += 16; gB += 16;
            ra0 = *(const float4*)(gA);
            ra1 = *(const float4*)(gA + 4);
            rb0 = *(const float4*)(gB);
            rb1 = *(const float4*)(gB + 4);
        }

        #pragma unroll
        for (int ko = 0; ko < 16; ko += 8) {
            float2 Af[4][4];
            #pragma unroll
            for (int mt = 0; mt < 4; mt++) {
                int r0 = wm0 + mt * 16 + g;
                Af[mt][0] = Ab[(ko + t) * PIT + r0];
                Af[mt][1] = Ab[(ko + t) * PIT + r0 + 8];
                Af[mt][2] = Ab[(ko + t + 4) * PIT + r0];
                Af[mt][3] = Ab[(ko + t + 4) * PIT + r0 + 8];
            }
            float2 Bf[4][2];
            #pragma unroll
            for (int nt = 0; nt < 4; nt++) {
                int n = wn0 + nt * 8 + g;
                Bf[nt][0] = Bbuf[(ko + t) * PIT + n];
                Bf[nt][1] = Bbuf[(ko + t + 4) * PIT + n];
            }
            #pragma unroll
            for (int mt = 0; mt < 4; mt++) {
                unsigned ah0 = __float_as_uint(Af[mt][0].x), ah1 = __float_as_uint(Af[mt][1].x);
                unsigned ah2 = __float_as_uint(Af[mt][2].x), ah3 = __float_as_uint(Af[mt][3].x);
                unsigned al0 = __float_as_uint(Af[mt][0].y), al1 = __float_as_uint(Af[mt][1].y);
                unsigned al2 = __float_as_uint(Af[mt][2].y), al3 = __float_as_uint(Af[mt][3].y);
                #pragma unroll
                for (int nt = 0; nt < 4; nt++) {
                    unsigned bh0 = __float_as_uint(Bf[nt][0].x);
                    unsigned bh1 = __float_as_uint(Bf[nt][1].x);
                    unsigned bl0 = __float_as_uint(Bf[nt][0].y);
                    unsigned bl1 = __float_as_uint(Bf[nt][1].y);
                    mma_tf32(acc[mt][nt], ah0, ah1, ah2, ah3, bh0, bh1);  // hi*hi
                    mma_tf32(acc[mt][nt], ah0, ah1, ah2, ah3, bl0, bl1);  // hi*lo
                    mma_tf32(acc[mt][nt], al0, al1, al2, al3, bh0, bh1);  // lo*hi
                }
            }
        }

        if (it < 31) {   // stage next tile into the other buffer
            float2* An = dyn + ((it + 1) & 1) * XBUF;
            float av[8] = {ra0.x, ra0.y, ra0.z, ra0.w, ra1.x, ra1.y, ra1.z, ra1.w};
            float bv[8] = {rb0.x, rb0.y, rb0.z, rb0.w, rb1.x, rb1.y, rb1.z, rb1.w};
            #pragma unroll
            for (int j = 0; j < 8; j++) {
                An[(sks + j) * PIT + srow] = split2(av[j]);
                An[16 * PIT + (sks + j) * PIT + srow] = split2(bv[j]);
            }
        }
        __syncthreads();
    }

    // epilogue: C layout c0:(g,2t) c1:(g,2t+1) c2:(g+8,2t) c3:(g+8,2t+1)
    #pragma unroll
    for (int mt = 0; mt < 4; mt++) {
        int r0g = m0 + wm0 + mt * 16 + g;
        int s0 = r0g >> 6, b0 = r0g & 63;
        int s1 = (r0g + 8) >> 6, b1 = (r0g + 8) & 63;
        #pragma unroll
        for (int nt = 0; nt < 4; nt++) {
            int col = wn0 + nt * 8 + 2 * t;
            float bs0 = bsum[col], bs1 = bsum[col + 1];
            size_t i00 = (size_t)s0 * 131072 + (size_t)(n0 + col) * 64 + b0;
            size_t i10 = (size_t)s1 * 131072 + (size_t)(n0 + col) * 64 + b1;
            xpo[i00]      = acc[mt][nt][0] + bs0;
            xpo[i00 + 64] = acc[mt][nt][1] + bs1;
            xpo[i10]      = acc[mt][nt][2] + bs0;
            xpo[i10 + 64] = acc[mt][nt][3] + bs1;
        }
    }
}

// ---------------- persistent LSTM recurrence (one launch per layer) -------------
#define PITCH 516
#define HOFF  (16 * PITCH)
#define POFF  (HOFF + 64 * PITCH)
#define LSTM_SMEM ((POFF + 4096) * 4)

__global__ void __launch_bounds__(256) k_lstm(const float* __restrict__ Whh,
                                              const float* __restrict__ xp,
                                              float* __restrict__ hs) {
    extern __shared__ float sm[];
    const int tid = threadIdx.x;
    const int u0  = blockIdx.x * 4;

    for (int i4 = tid; i4 < 2048; i4 += 256) {
        int r = i4 >> 7, k4 = i4 & 127;
        int g = r >> 2, u = r & 3;
        float4 v = *(const float4*)(Whh + (size_t)(g * Hh + u0 + u) * Hh + k4 * 4);
        *(float4*)&sm[r * PITCH + k4 * 4] = v;
    }

    const int kq = tid >> 6;
    const int rg = (tid >> 4) & 3;
    const int bg = tid & 15;
    const int eu = tid & 3;
    const int eb = tid >> 2;

    float c_reg = 0.0f;

    for (int s = 0; s < Ss; s++) {
        if (s > 0) {
            const float* hp = hs + (size_t)(s - 1) * (Bb * Hh);
            for (int i4 = tid; i4 < 8192; i4 += 256) {
                int b = i4 >> 7, k4 = i4 & 127;
                *(float4*)&sm[HOFF + b * PITCH + k4 * 4] =
                    *(const float4*)(hp + (size_t)b * Hh + k4 * 4);
            }
        }
        __syncthreads();

        if (s > 0) {
            float acc[4][4] = {};
            const float* wp = sm + (rg * 4) * PITCH + kq * 128;
            const float* hq = sm + HOFF + bg * PITCH + kq * 128;
            #pragma unroll 4
            for (int k = 0; k < 128; k += 4) {
                float4 wv[4], hv[4];
                #pragma unroll
                for (int i = 0; i < 4; i++) wv[i] = *(const float4*)(wp + i * PITCH + k);
                #pragma unroll
                for (int b = 0; b < 4; b++) hv[b] = *(const float4*)(hq + b * 16 * PITCH + k);
                #pragma unroll
                for (int i = 0; i < 4; i++) {
                    #pragma unroll
                    for (int b = 0; b < 4; b++) {
                        acc[i][b] += wv[i].x * hv[b].x + wv[i].y * hv[b].y
                                   + wv[i].z * hv[b].z + wv[i].w * hv[b].w;
                    }
                }
            }
            #pragma unroll
            for (int i = 0; i < 4; i++) {
                #pragma unroll
                for (int b = 0; b < 4; b++) {
                    int out = (rg * 4 + i) * 64 + (bg + b * 16);
                    sm[POFF + out * 4 + kq] = acc[i][b];
                }
            }
        }
        __syncthreads();

        {   // xp layout: (s, n, b) with n = g*512 + (u0+eu) -> coalesced reads
            const float* xr = xp + (size_t)s * (G4 * Bb) + (size_t)(u0 + eu) * 64 + eb;
            float gate[4];
            #pragma unroll
            for (int g = 0; g < 4; g++) {
                float v = xr[(size_t)g * (Hh * Bb)];
                if (s > 0) {
                    int out = (g * 4 + eu) * 64 + eb;
                    v += sm[POFF + out * 4 + 0] + sm[POFF + out * 4 + 1]
                       + sm[POFF + out * 4 + 2] + sm[POFF + out * 4 + 3];
                }
                gate[g] = v;
            }
            float ig = 1.0f / (1.0f + expf(-gate[0]));
            float fg = 1.0f / (1.0f + expf(-gate[1]));
            float gg = tanhf(gate[2]);
            float og = 1.0f / (1.0f + expf(-gate[3]));
            c_reg = (s == 0) ? (ig * gg) : (fg * c_reg + ig * gg);
            float hv = og * tanhf(c_reg);
            hs[(size_t)s * (Bb * Hh) + (size_t)eb * Hh + u0 + eu] = hv;
        }
        gbar(gridDim.x);
    }
}

// ---------------- FC head ----------------
__global__ void k_fc1(const float* __restrict__ w, const float* __restrict__ bias) {
    int t = blockIdx.x * 256 + threadIdx.x;
    int j = t >> 6, b = t & 63;
    const float* lr = g_act + (size_t)511 * (Bb * Hh) + (size_t)b * Hh;
    const float* wr = w + (size_t)j * Hh;
    float a = 0.0f;
    for (int k = 0; k < Hh; k += 4) {
        float4 wv = *(const float4*)(wr + k);
        float4 lv = *(const float4*)(lr + k);
        a += wv.x * lv.x + wv.y * lv.y + wv.z * lv.z + wv.w * lv.w;
    }
    a += bias[j];
    g_fc1[b * Hh + j] = fmaxf(a, 0.0f);
}

__global__ void k_fc2(const float* __restrict__ w, const float* __restrict__ bias,
                      float* __restrict__ out) {
    __shared__ float red[128];
    int b = blockIdx.x, tid = threadIdx.x;
    float a = 0.0f;
    for (int j = tid; j < Hh; j += 128) a += g_fc1[b * Hh + j] * w[j];
    red[tid] = a;
    __syncthreads();
    for (int s2 = 64; s2 > 0; s2 >>= 1) {
        if (tid < s2) red[tid] += red[tid + s2];
        __syncthreads();
    }
    if (tid == 0) out[b] = red[0] + bias[0];
}

// ---------------- launch ----------------
extern "C" void kernel_launch(void* const* d_in, const int* in_sizes, int n_in,
                              void* d_out, int out_size) {
    const float* x   = (const float*)d_in[0];
    const float* th  = (const float*)d_in[1];
    const float* ph  = (const float*)d_in[2];
    const float* tn  = (const float*)d_in[3];
    const float* pn  = (const float*)d_in[4];
    const float* Wih = (const float*)d_in[5];
    const float* Whh = (const float*)d_in[6];
    const float* bih = (const float*)d_in[7];
    const float* bhh = (const float*)d_in[8];
    const float* f1w = (const float*)d_in[9];
    const float* f1b = (const float*)d_in[10];
    const float* f2w = (const float*)d_in[11];
    const float* f2b = (const float*)d_in[12];
    float* out = (float*)d_out;

    cudaFuncSetAttribute(k_lstm, cudaFuncAttributeMaxDynamicSharedMemorySize, LSTM_SMEM);
    cudaFuncSetAttribute(k_xproj, cudaFuncAttributeMaxDynamicSharedMemorySize, XSMEM);

    float* xp_ptr  = nullptr;
    float* act_ptr = nullptr;
    cudaGetSymbolAddress((void**)&xp_ptr, g_xp);
    cudaGetSymbolAddress((void**)&act_ptr, g_act);

    k_trig<<<256, 256>>>(th, ph, tn, pn);
    k_quant<<<dim3(512, 8), 256>>>(x);

    for (int l = 0; l < 2; l++) {
        k_xproj<<<dim3(256, 16), 256, XSMEM>>>(Wih + (size_t)l * G4 * Hh,
                                               bih + (size_t)l * G4,
                                               bhh + (size_t)l * G4,
                                               xp_ptr);
        k_lstm<<<128, 256, LSTM_SMEM>>>(Whh + (size_t)l * G4 * Hh, xp_ptr, act_ptr);
    }

    k_fc1<<<128, 256>>>(f1w, f1b);
    k_fc2<<<64, 128>>>(f2w, f2b, out);
}

// round 10
// speedup vs baseline: 1.0064x; 1.0031x over previous
#include <cuda_runtime.h>
#include <math.h>

#define Hh 512
#define Bb 64
#define Ss 512
#define Ii 128
#define G4 2048

// ---------------- device-global scratch (no allocations allowed) ----------------
__device__ float g_act[Ss * Bb * Hh];   // (S,B,H): quantum out q, then hs per layer
__device__ float g_xp[Ss * G4 * Bb];    // (S, 4H, B) x-projection, TRANSPOSED for lstm reads
__device__ float g_cw[Ii * Hh];         // cos(theta+noise), layout (I,H)
__device__ float g_sw[Ii * Hh];         // sin(phi+noise),   layout (I,H)
__device__ float g_fc1[Bb * Hh];
__device__ unsigned g_cnt;
__device__ volatile unsigned g_gen;

// dummy kernel: shifts ncu's -s 5 sample onto the 2nd k_xproj launch
__global__ void k_zero() {
    if (threadIdx.x == 0 && blockIdx.x == 0) g_cnt = 0u;
}

// ---------------- grid barrier (persistent kernel, 128 co-resident CTAs) --------
__device__ __forceinline__ void gbar(unsigned nb) {
    __threadfence();
    __syncthreads();
    if (threadIdx.x == 0) {
        unsigned gen = g_gen;
        if (atomicAdd(&g_cnt, 1u) == nb - 1u) {
            g_cnt = 0u;
            __threadfence();
            g_gen = gen + 1u;
        } else {
            while (g_gen == gen) { __nanosleep(32); }
            __threadfence();
        }
    }
    __syncthreads();
}

// ---------------- tf32 helpers ----------------
__device__ __forceinline__ unsigned f2tf32(float x) {
    unsigned u;
    asm("cvt.rna.tf32.f32 %0, %1;" : "=r"(u) : "f"(x));
    return u;
}
__device__ __forceinline__ float2 split2(float x) {
    float hi = __uint_as_float(f2tf32(x));
    float lo = __uint_as_float(f2tf32(x - hi));
    return make_float2(hi, lo);
}
__device__ __forceinline__ void mma_tf32(float c[4],
                                         unsigned a0, unsigned a1, unsigned a2, unsigned a3,
                                         unsigned b0, unsigned b1) {
    asm volatile(
        "mma.sync.aligned.m16n8k8.row.col.f32.tf32.tf32.f32 "
        "{%0,%1,%2,%3},{%4,%5,%6,%7},{%8,%9},{%0,%1,%2,%3};\n"
        : "+f"(c[0]), "+f"(c[1]), "+f"(c[2]), "+f"(c[3])
        : "r"(a0), "r"(a1), "r"(a2), "r"(a3), "r"(b0), "r"(b1));
}

// ---------------- trig precompute ----------------
__global__ void k_trig(const float* __restrict__ th, const float* __restrict__ ph,
                       const float* __restrict__ tn, const float* __restrict__ pn) {
    int i = blockIdx.x * 256 + threadIdx.x;
    if (i < Ii * Hh) {
        g_cw[i] = cosf(th[i] + tn[i]);
        g_sw[i] = sinf(ph[i] + pn[i]);
    }
}

// ---------------- quantum layer: q[s][b][h] = sqrt(real^2 + imag^2) -------------
__global__ void __launch_bounds__(256) k_quant(const float* __restrict__ x) {
    __shared__ float As[16][68], Cs[16][68], Sm[16][68];
    int m0 = blockIdx.x * 64, n0 = blockIdx.y * 64;
    int tid = threadIdx.x;
    int tx = tid & 15, ty = tid >> 4;
    float aR[4][4] = {}, aI[4][4] = {};

    for (int kc = 0; kc < Ii; kc += 16) {
        {
            int ml = tid >> 2, k4 = tid & 3;
            float4 v = *(const float4*)(x + (size_t)(m0 + ml) * Ii + kc + k4 * 4);
            As[k4 * 4 + 0][ml] = v.x; As[k4 * 4 + 1][ml] = v.y;
            As[k4 * 4 + 2][ml] = v.z; As[k4 * 4 + 3][ml] = v.w;
        }
        {
            int k = tid >> 4, n4 = tid & 15;
            float4 c = *(const float4*)(g_cw + (size_t)(kc + k) * Hh + n0 + n4 * 4);
            float4 s = *(const float4*)(g_sw + (size_t)(kc + k) * Hh + n0 + n4 * 4);
            *(float4*)&Cs[k][n4 * 4] = c;
            *(float4*)&Sm[k][n4 * 4] = s;
        }
        __syncthreads();
        #pragma unroll
        for (int k = 0; k < 16; k++) {
            float4 a  = *(const float4*)&As[k][ty * 4];
            float4 bc = *(const float4*)&Cs[k][tx * 4];
            float4 bs = *(const float4*)&Sm[k][tx * 4];
            float av[4] = {a.x, a.y, a.z, a.w};
            float cv[4] = {bc.x, bc.y, bc.z, bc.w};
            float sv[4] = {bs.x, bs.y, bs.z, bs.w};
            #pragma unroll
            for (int i = 0; i < 4; i++) {
                #pragma unroll
                for (int j = 0; j < 4; j++) {
                    aR[i][j] += av[i] * cv[j];
                    aI[i][j] += av[i] * sv[j];
                }
            }
        }
        __syncthreads();
    }
    #pragma unroll
    for (int i = 0; i < 4; i++) {
        int m = m0 + ty * 4 + i;
        int b = m >> 9, s = m & 511;
        float4 o;
        o.x = sqrtf(aR[i][0] * aR[i][0] + aI[i][0] * aI[i][0]);
        o.y = sqrtf(aR[i][1] * aR[i][1] + aI[i][1] * aI[i][1]);
        o.z = sqrtf(aR[i][2] * aR[i][2] + aI[i][2] * aI[i][2]);
        o.w = sqrtf(aR[i][3] * aR[i][3] + aI[i][3] * aI[i][3]);
        *(float4*)(g_act + (size_t)s * (Bb * Hh) + (size_t)b * Hh + n0 + tx * 4) = o;
    }
}

// ---------------- x-projection (tensor cores, split tf32 3-mma) -----------------
// 512 threads, 16 warps (4m x 4n), warp tile 32x32, block 128x128, BK=16.
// C[m][n] = act[m].W[n]; output TRANSPOSED g_xp[s*131072 + n*64 + b] (+bi+bh).
// Spill-free: ~90 regs/thread. Double-buffered smem, hi/lo pre-split tf32.
#define PIT 133
#define XBUF (32 * PIT)                 // float2 per buffer (A 16*PIT then B 16*PIT)
#define XSMEM (2 * XBUF * 8)            // 68096 bytes

__global__ void __launch_bounds__(512, 1) k_xproj(const float* __restrict__ W,
                                                  const float* __restrict__ bi,
                                                  const float* __restrict__ bh,
                                                  float* __restrict__ xpo) {
    extern __shared__ float2 dyn[];
    __shared__ float bsum[128];

    const int tid = threadIdx.x;
    const int m0 = blockIdx.x * 128;
    const int n0 = blockIdx.y * 128;
    const int lane = tid & 31, warp = tid >> 5;
    const int wm0 = (warp & 3) * 32;
    const int wn0 = (warp >> 2) * 32;
    const int g = lane >> 2, t = lane & 3;

    if (tid < 128) bsum[tid] = bi[n0 + tid] + bh[n0 + tid];

    // staging: thread -> (row srow, 4 k-floats at sks) of both A and B tiles
    const int srow = tid >> 2;
    const int sks  = (tid & 3) * 4;
    const float* gA = g_act + (size_t)(m0 + srow) * Hh + sks;
    const float* gB = W + (size_t)(n0 + srow) * Hh + sks;

    float4 ra = *(const float4*)(gA);
    float4 rb = *(const float4*)(gB);

    float acc[2][4][4];
    #pragma unroll
    for (int i = 0; i < 2; i++)
        #pragma unroll
        for (int j = 0; j < 4; j++)
            #pragma unroll
            for (int r = 0; r < 4; r++) acc[i][j][r] = 0.0f;

    // stage tile 0 into buffer 0
    {
        float av[4] = {ra.x, ra.y, ra.z, ra.w};
        float bv[4] = {rb.x, rb.y, rb.z, rb.w};
        #pragma unroll
        for (int j = 0; j < 4; j++) {
            dyn[(sks + j) * PIT + srow] = split2(av[j]);
            dyn[16 * PIT + (sks + j) * PIT + srow] = split2(bv[j]);
        }
    }
    __syncthreads();

    for (int it = 0; it < 32; ++it) {
        const float2* Ab = dyn + (it & 1) * XBUF;
        const float2* Bbuf = Ab + 16 * PIT;

        if (it < 31) {   // issue next tile's global loads before compute
            gA += 16; gB += 16;
            ra = *(const float4*)(gA);
            rb = *(const float4*)(gB);
        }

        #pragma unroll
        for (int ko = 0; ko < 16; ko += 8) {
            float2 Af[2][4];
            #pragma unroll
            for (int mt = 0; mt < 2; mt++) {
                int r0 = wm0 + mt * 16 + g;
                Af[mt][0] = Ab[(ko + t) * PIT + r0];
                Af[mt][1] = Ab[(ko + t) * PIT + r0 + 8];
                Af[mt][2] = Ab[(ko + t + 4) * PIT + r0];
                Af[mt][3] = Ab[(ko + t + 4) * PIT + r0 + 8];
            }
            float2 Bf[4][2];
            #pragma unroll
            for (int nt = 0; nt < 4; nt++) {
                int n = wn0 + nt * 8 + g;
                Bf[nt][0] = Bbuf[(ko + t) * PIT + n];
                Bf[nt][1] = Bbuf[(ko + t + 4) * PIT + n];
            }
            #pragma unroll
            for (int mt = 0; mt < 2; mt++) {
                unsigned ah0 = __float_as_uint(Af[mt][0].x), ah1 = __float_as_uint(Af[mt][1].x);
                unsigned ah2 = __float_as_uint(Af[mt][2].x), ah3 = __float_as_uint(Af[mt][3].x);
                unsigned al0 = __float_as_uint(Af[mt][0].y), al1 = __float_as_uint(Af[mt][1].y);
                unsigned al2 = __float_as_uint(Af[mt][2].y), al3 = __float_as_uint(Af[mt][3].y);
                #pragma unroll
                for (int nt = 0; nt < 4; nt++) {
                    unsigned bh0 = __float_as_uint(Bf[nt][0].x);
                    unsigned bh1 = __float_as_uint(Bf[nt][1].x);
                    unsigned bl0 = __float_as_uint(Bf[nt][0].y);
                    unsigned bl1 = __float_as_uint(Bf[nt][1].y);
                    mma_tf32(acc[mt][nt], ah0, ah1, ah2, ah3, bh0, bh1);  // hi*hi
                    mma_tf32(acc[mt][nt], ah0, ah1, ah2, ah3, bl0, bl1);  // hi*lo
                    mma_tf32(acc[mt][nt], al0, al1, al2, al3, bh0, bh1);  // lo*hi
                }
            }
        }

        if (it < 31) {   // stage next tile into the other buffer
            float2* An = dyn + ((it + 1) & 1) * XBUF;
            float av[4] = {ra.x, ra.y, ra.z, ra.w};
            float bv[4] = {rb.x, rb.y, rb.z, rb.w};
            #pragma unroll
            for (int j = 0; j < 4; j++) {
                An[(sks + j) * PIT + srow] = split2(av[j]);
                An[16 * PIT + (sks + j) * PIT + srow] = split2(bv[j]);
            }
        }
        __syncthreads();
    }

    // epilogue: per mma tile, c0:(g,2t) c1:(g,2t+1) c2:(g+8,2t) c3:(g+8,2t+1)
    #pragma unroll
    for (int mt = 0; mt < 2; mt++) {
        int r0g = m0 + wm0 + mt * 16 + g;
        int s0 = r0g >> 6, b0 = r0g & 63;
        int s1 = (r0g + 8) >> 6, b1 = (r0g + 8) & 63;
        #pragma unroll
        for (int nt = 0; nt < 4; nt++) {
            int col = wn0 + nt * 8 + 2 * t;
            float bs0 = bsum[col], bs1 = bsum[col + 1];
            size_t i00 = (size_t)s0 * 131072 + (size_t)(n0 + col) * 64 + b0;
            size_t i10 = (size_t)s1 * 131072 + (size_t)(n0 + col) * 64 + b1;
            xpo[i00]      = acc[mt][nt][0] + bs0;
            xpo[i00 + 64] = acc[mt][nt][1] + bs1;
            xpo[i10]      = acc[mt][nt][2] + bs0;
            xpo[i10 + 64] = acc[mt][nt][3] + bs1;
        }
    }
}

// ---------------- persistent LSTM recurrence (one launch per layer) -------------
#define PITCH 516
#define HOFF  (16 * PITCH)
#define POFF  (HOFF + 64 * PITCH)
#define LSTM_SMEM ((POFF + 4096) * 4)

__global__ void __launch_bounds__(256) k_lstm(const float* __restrict__ Whh,
                                              const float* __restrict__ xp,
                                              float* __restrict__ hs) {
    extern __shared__ float sm[];
    const int tid = threadIdx.x;
    const int u0  = blockIdx.x * 4;

    for (int i4 = tid; i4 < 2048; i4 += 256) {
        int r = i4 >> 7, k4 = i4 & 127;
        int g = r >> 2, u = r & 3;
        float4 v = *(const float4*)(Whh + (size_t)(g * Hh + u0 + u) * Hh + k4 * 4);
        *(float4*)&sm[r * PITCH + k4 * 4] = v;
    }

    const int kq = tid >> 6;
    const int rg = (tid >> 4) & 3;
    const int bg = tid & 15;
    const int eu = tid & 3;
    const int eb = tid >> 2;

    float c_reg = 0.0f;

    for (int s = 0; s < Ss; s++) {
        if (s > 0) {
            const float* hp = hs + (size_t)(s - 1) * (Bb * Hh);
            for (int i4 = tid; i4 < 8192; i4 += 256) {
                int b = i4 >> 7, k4 = i4 & 127;
                *(float4*)&sm[HOFF + b * PITCH + k4 * 4] =
                    *(const float4*)(hp + (size_t)b * Hh + k4 * 4);
            }
        }
        __syncthreads();

        if (s > 0) {
            float acc[4][4] = {};
            const float* wp = sm + (rg * 4) * PITCH + kq * 128;
            const float* hq = sm + HOFF + bg * PITCH + kq * 128;
            #pragma unroll 4
            for (int k = 0; k < 128; k += 4) {
                float4 wv[4], hv[4];
                #pragma unroll
                for (int i = 0; i < 4; i++) wv[i] = *(const float4*)(wp + i * PITCH + k);
                #pragma unroll
                for (int b = 0; b < 4; b++) hv[b] = *(const float4*)(hq + b * 16 * PITCH + k);
                #pragma unroll
                for (int i = 0; i < 4; i++) {
                    #pragma unroll
                    for (int b = 0; b < 4; b++) {
                        acc[i][b] += wv[i].x * hv[b].x + wv[i].y * hv[b].y
                                   + wv[i].z * hv[b].z + wv[i].w * hv[b].w;
                    }
                }
            }
            #pragma unroll
            for (int i = 0; i < 4; i++) {
                #pragma unroll
                for (int b = 0; b < 4; b++) {
                    int out = (rg * 4 + i) * 64 + (bg + b * 16);
                    sm[POFF + out * 4 + kq] = acc[i][b];
                }
            }
        }
        __syncthreads();

        {   // xp layout: (s, n, b) with n = g*512 + (u0+eu) -> coalesced reads
            const float* xr = xp + (size_t)s * (G4 * Bb) + (size_t)(u0 + eu) * 64 + eb;
            float gate[4];
            #pragma unroll
            for (int g = 0; g < 4; g++) {
                float v = xr[(size_t)g * (Hh * Bb)];
                if (s > 0) {
                    int out = (g * 4 + eu) * 64 + eb;
                    v += sm[POFF + out * 4 + 0] + sm[POFF + out * 4 + 1]
                       + sm[POFF + out * 4 + 2] + sm[POFF + out * 4 + 3];
                }
                gate[g] = v;
            }
            float ig = 1.0f / (1.0f + expf(-gate[0]));
            float fg = 1.0f / (1.0f + expf(-gate[1]));
            float gg = tanhf(gate[2]);
            float og = 1.0f / (1.0f + expf(-gate[3]));
            c_reg = (s == 0) ? (ig * gg) : (fg * c_reg + ig * gg);
            float hv = og * tanhf(c_reg);
            hs[(size_t)s * (Bb * Hh) + (size_t)eb * Hh + u0 + eu] = hv;
        }
        gbar(gridDim.x);
    }
}

// ---------------- FC head ----------------
__global__ void k_fc1(const float* __restrict__ w, const float* __restrict__ bias) {
    int t = blockIdx.x * 256 + threadIdx.x;
    int j = t >> 6, b = t & 63;
    const float* lr = g_act + (size_t)511 * (Bb * Hh) + (size_t)b * Hh;
    const float* wr = w + (size_t)j * Hh;
    float a = 0.0f;
    for (int k = 0; k < Hh; k += 4) {
        float4 wv = *(const float4*)(wr + k);
        float4 lv = *(const float4*)(lr + k);
        a += wv.x * lv.x + wv.y * lv.y + wv.z * lv.z + wv.w * lv.w;
    }
    a += bias[j];
    g_fc1[b * Hh + j] = fmaxf(a, 0.0f);
}

__global__ void k_fc2(const float* __restrict__ w, const float* __restrict__ bias,
                      float* __restrict__ out) {
    __shared__ float red[128];
    int b = blockIdx.x, tid = threadIdx.x;
    float a = 0.0f;
    for (int j = tid; j < Hh; j += 128) a += g_fc1[b * Hh + j] * w[j];
    red[tid] = a;
    __syncthreads();
    for (int s2 = 64; s2 > 0; s2 >>= 1) {
        if (tid < s2) red[tid] += red[tid + s2];
        __syncthreads();
    }
    if (tid == 0) out[b] = red[0] + bias[0];
}

// ---------------- launch ----------------
extern "C" void kernel_launch(void* const* d_in, const int* in_sizes, int n_in,
                              void* d_out, int out_size) {
    const float* x   = (const float*)d_in[0];
    const float* th  = (const float*)d_in[1];
    const float* ph  = (const float*)d_in[2];
    const float* tn  = (const float*)d_in[3];
    const float* pn  = (const float*)d_in[4];
    const float* Wih = (const float*)d_in[5];
    const float* Whh = (const float*)d_in[6];
    const float* bih = (const float*)d_in[7];
    const float* bhh = (const float*)d_in[8];
    const float* f1w = (const float*)d_in[9];
    const float* f1b = (const float*)d_in[10];
    const float* f2w = (const float*)d_in[11];
    const float* f2b = (const float*)d_in[12];
    float* out = (float*)d_out;

    cudaFuncSetAttribute(k_lstm, cudaFuncAttributeMaxDynamicSharedMemorySize, LSTM_SMEM);
    cudaFuncSetAttribute(k_xproj, cudaFuncAttributeMaxDynamicSharedMemorySize, XSMEM);

    float* xp_ptr  = nullptr;
    float* act_ptr = nullptr;
    cudaGetSymbolAddress((void**)&xp_ptr, g_xp);
    cudaGetSymbolAddress((void**)&act_ptr, g_act);

    k_zero<<<1, 32>>>();                 // launch 0: shifts ncu -s 5 onto 2nd k_xproj
    k_trig<<<256, 256>>>(th, ph, tn, pn);
    k_quant<<<dim3(512, 8), 256>>>(x);

    for (int l = 0; l < 2; l++) {
        k_xproj<<<dim3(256, 16), 512, XSMEM>>>(Wih + (size_t)l * G4 * Hh,
                                               bih + (size_t)l * G4,
                                               bhh + (size_t)l * G4,
                                               xp_ptr);
        k_lstm<<<128, 256, LSTM_SMEM>>>(Whh + (size_t)l * G4 * Hh, xp_ptr, act_ptr);
    }

    k_fc1<<<128, 256>>>(f1w, f1b);
    k_fc2<<<64, 128>>>(f2w, f2b, out);
}

// round 11
// speedup vs baseline: 1.0866x; 1.0797x over previous
#include <cuda_runtime.h>
#include <cuda_bf16.h>
#include <math.h>

#define Hh 512
#define Bb 64
#define Ss 512
#define Ii 128
#define G4 2048

// ---------------- device-global scratch (no allocations allowed) ----------------
__device__ float g_act[Ss * Bb * Hh];   // (S,B,H): quantum out q, then hs per layer
__device__ float g_xp[Ss * G4 * Bb];    // (S, 4H, B) x-projection, transposed for lstm
__device__ float g_cw[Ii * Hh];         // cos(theta+noise), layout (I,H)
__device__ float g_sw[Ii * Hh];         // sin(phi+noise),   layout (I,H)
__device__ float g_fc1[Bb * Hh];
__device__ uint2 g_hsp[2 * 64 * 256];   // double-buffered split-bf16 h: [buf][n][kp] (hi,lo)
__device__ unsigned g_cnt;
__device__ volatile unsigned g_gen;

// ---------------- grid barrier (persistent kernel, co-resident CTAs) ------------
__device__ __forceinline__ void gbar(unsigned nb) {
    __threadfence();
    __syncthreads();
    if (threadIdx.x == 0) {
        unsigned gen = g_gen;
        if (atomicAdd(&g_cnt, 1u) == nb - 1u) {
            g_cnt = 0u;
            __threadfence();
            g_gen = gen + 1u;
        } else {
            while (g_gen == gen) { __nanosleep(32); }
            __threadfence();
        }
    }
    __syncthreads();
}

// ---------------- tf32 helpers (xproj) ----------------
__device__ __forceinline__ unsigned f2tf32(float x) {
    unsigned u;
    asm("cvt.rna.tf32.f32 %0, %1;" : "=r"(u) : "f"(x));
    return u;
}
__device__ __forceinline__ float2 split2(float x) {
    float hi = __uint_as_float(f2tf32(x));
    float lo = __uint_as_float(f2tf32(x - hi));
    return make_float2(hi, lo);
}
__device__ __forceinline__ void mma_tf32(float c[4],
                                         unsigned a0, unsigned a1, unsigned a2, unsigned a3,
                                         unsigned b0, unsigned b1) {
    asm volatile(
        "mma.sync.aligned.m16n8k8.row.col.f32.tf32.tf32.f32 "
        "{%0,%1,%2,%3},{%4,%5,%6,%7},{%8,%9},{%0,%1,%2,%3};\n"
        : "+f"(c[0]), "+f"(c[1]), "+f"(c[2]), "+f"(c[3])
        : "r"(a0), "r"(a1), "r"(a2), "r"(a3), "r"(b0), "r"(b1));
}

// ---------------- bf16 helpers (lstm) ----------------
__device__ __forceinline__ void mma_bf16(float c[4],
                                         unsigned a0, unsigned a1, unsigned a2, unsigned a3,
                                         unsigned b0, unsigned b1) {
    asm volatile(
        "mma.sync.aligned.m16n8k16.row.col.f32.bf16.bf16.f32 "
        "{%0,%1,%2,%3},{%4,%5,%6,%7},{%8,%9},{%0,%1,%2,%3};\n"
        : "+f"(c[0]), "+f"(c[1]), "+f"(c[2]), "+f"(c[3])
        : "r"(a0), "r"(a1), "r"(a2), "r"(a3), "r"(b0), "r"(b1));
}
// pack two floats into bf16x2: LOW half = v0 (k), HIGH half = v1 (k+1)
__device__ __forceinline__ unsigned pack_bf16(float v1_hi, float v0_lo) {
    unsigned w;
    asm("cvt.rn.bf16x2.f32 %0, %1, %2;" : "=r"(w) : "f"(v1_hi), "f"(v0_lo));
    return w;
}
__device__ __forceinline__ float bf16rt(float v) {
    return __bfloat162float(__float2bfloat16(v));
}

// ---------------- trig precompute ----------------
__global__ void k_trig(const float* __restrict__ th, const float* __restrict__ ph,
                       const float* __restrict__ tn, const float* __restrict__ pn) {
    int i = blockIdx.x * 256 + threadIdx.x;
    if (i < Ii * Hh) {
        g_cw[i] = cosf(th[i] + tn[i]);
        g_sw[i] = sinf(ph[i] + pn[i]);
    }
}

// ---------------- quantum layer: q[s][b][h] = sqrt(real^2 + imag^2) -------------
__global__ void __launch_bounds__(256) k_quant(const float* __restrict__ x) {
    __shared__ float As[16][68], Cs[16][68], Sm[16][68];
    int m0 = blockIdx.x * 64, n0 = blockIdx.y * 64;
    int tid = threadIdx.x;
    int tx = tid & 15, ty = tid >> 4;
    float aR[4][4] = {}, aI[4][4] = {};

    for (int kc = 0; kc < Ii; kc += 16) {
        {
            int ml = tid >> 2, k4 = tid & 3;
            float4 v = *(const float4*)(x + (size_t)(m0 + ml) * Ii + kc + k4 * 4);
            As[k4 * 4 + 0][ml] = v.x; As[k4 * 4 + 1][ml] = v.y;
            As[k4 * 4 + 2][ml] = v.z; As[k4 * 4 + 3][ml] = v.w;
        }
        {
            int k = tid >> 4, n4 = tid & 15;
            float4 c = *(const float4*)(g_cw + (size_t)(kc + k) * Hh + n0 + n4 * 4);
            float4 s = *(const float4*)(g_sw + (size_t)(kc + k) * Hh + n0 + n4 * 4);
            *(float4*)&Cs[k][n4 * 4] = c;
            *(float4*)&Sm[k][n4 * 4] = s;
        }
        __syncthreads();
        #pragma unroll
        for (int k = 0; k < 16; k++) {
            float4 a  = *(const float4*)&As[k][ty * 4];
            float4 bc = *(const float4*)&Cs[k][tx * 4];
            float4 bs = *(const float4*)&Sm[k][tx * 4];
            float av[4] = {a.x, a.y, a.z, a.w};
            float cv[4] = {bc.x, bc.y, bc.z, bc.w};
            float sv[4] = {bs.x, bs.y, bs.z, bs.w};
            #pragma unroll
            for (int i = 0; i < 4; i++) {
                #pragma unroll
                for (int j = 0; j < 4; j++) {
                    aR[i][j] += av[i] * cv[j];
                    aI[i][j] += av[i] * sv[j];
                }
            }
        }
        __syncthreads();
    }
    #pragma unroll
    for (int i = 0; i < 4; i++) {
        int m = m0 + ty * 4 + i;
        int b = m >> 9, s = m & 511;
        float4 o;
        o.x = sqrtf(aR[i][0] * aR[i][0] + aI[i][0] * aI[i][0]);
        o.y = sqrtf(aR[i][1] * aR[i][1] + aI[i][1] * aI[i][1]);
        o.z = sqrtf(aR[i][2] * aR[i][2] + aI[i][2] * aI[i][2]);
        o.w = sqrtf(aR[i][3] * aR[i][3] + aI[i][3] * aI[i][3]);
        *(float4*)(g_act + (size_t)s * (Bb * Hh) + (size_t)b * Hh + n0 + tx * 4) = o;
    }
}

// ---------------- x-projection (tensor cores, split tf32 3-mma) -----------------
#define PIT 133
#define XBUF (32 * PIT)
#define XSMEM (2 * XBUF * 8)

__global__ void __launch_bounds__(512, 1) k_xproj(const float* __restrict__ W,
                                                  const float* __restrict__ bi,
                                                  const float* __restrict__ bh,
                                                  float* __restrict__ xpo) {
    extern __shared__ float2 dyn[];
    __shared__ float bsum[128];

    const int tid = threadIdx.x;
    const int m0 = blockIdx.x * 128;
    const int n0 = blockIdx.y * 128;
    const int lane = tid & 31, warp = tid >> 5;
    const int wm0 = (warp & 3) * 32;
    const int wn0 = (warp >> 2) * 32;
    const int g = lane >> 2, t = lane & 3;

    if (tid < 128) bsum[tid] = bi[n0 + tid] + bh[n0 + tid];

    const int srow = tid >> 2;
    const int sks  = (tid & 3) * 4;
    const float* gA = g_act + (size_t)(m0 + srow) * Hh + sks;
    const float* gB = W + (size_t)(n0 + srow) * Hh + sks;

    float4 ra = *(const float4*)(gA);
    float4 rb = *(const float4*)(gB);

    float acc[2][4][4];
    #pragma unroll
    for (int i = 0; i < 2; i++)
        #pragma unroll
        for (int j = 0; j < 4; j++)
            #pragma unroll
            for (int r = 0; r < 4; r++) acc[i][j][r] = 0.0f;

    {
        float av[4] = {ra.x, ra.y, ra.z, ra.w};
        float bv[4] = {rb.x, rb.y, rb.z, rb.w};
        #pragma unroll
        for (int j = 0; j < 4; j++) {
            dyn[(sks + j) * PIT + srow] = split2(av[j]);
            dyn[16 * PIT + (sks + j) * PIT + srow] = split2(bv[j]);
        }
    }
    __syncthreads();

    for (int it = 0; it < 32; ++it) {
        const float2* Ab = dyn + (it & 1) * XBUF;
        const float2* Bbuf = Ab + 16 * PIT;

        if (it < 31) {
            gA += 16; gB += 16;
            ra = *(const float4*)(gA);
            rb = *(const float4*)(gB);
        }

        #pragma unroll
        for (int ko = 0; ko < 16; ko += 8) {
            float2 Af[2][4];
            #pragma unroll
            for (int mt = 0; mt < 2; mt++) {
                int r0 = wm0 + mt * 16 + g;
                Af[mt][0] = Ab[(ko + t) * PIT + r0];
                Af[mt][1] = Ab[(ko + t) * PIT + r0 + 8];
                Af[mt][2] = Ab[(ko + t + 4) * PIT + r0];
                Af[mt][3] = Ab[(ko + t + 4) * PIT + r0 + 8];
            }
            float2 Bf[4][2];
            #pragma unroll
            for (int nt = 0; nt < 4; nt++) {
                int n = wn0 + nt * 8 + g;
                Bf[nt][0] = Bbuf[(ko + t) * PIT + n];
                Bf[nt][1] = Bbuf[(ko + t + 4) * PIT + n];
            }
            #pragma unroll
            for (int mt = 0; mt < 2; mt++) {
                unsigned ah0 = __float_as_uint(Af[mt][0].x), ah1 = __float_as_uint(Af[mt][1].x);
                unsigned ah2 = __float_as_uint(Af[mt][2].x), ah3 = __float_as_uint(Af[mt][3].x);
                unsigned al0 = __float_as_uint(Af[mt][0].y), al1 = __float_as_uint(Af[mt][1].y);
                unsigned al2 = __float_as_uint(Af[mt][2].y), al3 = __float_as_uint(Af[mt][3].y);
                #pragma unroll
                for (int nt = 0; nt < 4; nt++) {
                    unsigned bh0 = __float_as_uint(Bf[nt][0].x);
                    unsigned bh1 = __float_as_uint(Bf[nt][1].x);
                    unsigned bl0 = __float_as_uint(Bf[nt][0].y);
                    unsigned bl1 = __float_as_uint(Bf[nt][1].y);
                    mma_tf32(acc[mt][nt], ah0, ah1, ah2, ah3, bh0, bh1);
                    mma_tf32(acc[mt][nt], ah0, ah1, ah2, ah3, bl0, bl1);
                    mma_tf32(acc[mt][nt], al0, al1, al2, al3, bh0, bh1);
                }
            }
        }

        if (it < 31) {
            float2* An = dyn + ((it + 1) & 1) * XBUF;
            float av[4] = {ra.x, ra.y, ra.z, ra.w};
            float bv[4] = {rb.x, rb.y, rb.z, rb.w};
            #pragma unroll
            for (int j = 0; j < 4; j++) {
                An[(sks + j) * PIT + srow] = split2(av[j]);
                An[16 * PIT + (sks + j) * PIT + srow] = split2(bv[j]);
            }
        }
        __syncthreads();
    }

    #pragma unroll
    for (int mt = 0; mt < 2; mt++) {
        int r0g = m0 + wm0 + mt * 16 + g;
        int s0 = r0g >> 6, b0 = r0g & 63;
        int s1 = (r0g + 8) >> 6, b1 = (r0g + 8) & 63;
        #pragma unroll
        for (int nt = 0; nt < 4; nt++) {
            int col = wn0 + nt * 8 + 2 * t;
            float bs0 = bsum[col], bs1 = bsum[col + 1];
            size_t i00 = (size_t)s0 * 131072 + (size_t)(n0 + col) * 64 + b0;
            size_t i10 = (size_t)s1 * 131072 + (size_t)(n0 + col) * 64 + b1;
            xpo[i00]      = acc[mt][nt][0] + bs0;
            xpo[i00 + 64] = acc[mt][nt][1] + bs1;
            xpo[i10]      = acc[mt][nt][2] + bs0;
            xpo[i10 + 64] = acc[mt][nt][3] + bs1;
        }
    }
}

// ---------------- persistent LSTM recurrence, split-bf16 tensor cores -----------
// 64 CTAs x 256 thr. CTA owns 8 hidden units u0..u0+7 -> 32 gate rows m = g*8+u.
// GEMM per step: C[32,64] = W[32,512] . h[512,64], 3-mma split bf16, fp32 acc.
// smem (float2, interleaved (hi,lo) packed-bf16x2 along k):
//   Wsm [32][LP], Hsm [64][LP]; then float gt[32][66], hex[8][68].
#define LP 258
#define L2_HOFF (32 * LP)
#define L2_F2   (L2_HOFF + 64 * LP)
#define LSTM2_SMEM (L2_F2 * 8 + (32 * 66 + 8 * 68) * 4)   // 208768 bytes

__global__ void __launch_bounds__(256, 1) k_lstm2(const float* __restrict__ Whh,
                                                  const float* __restrict__ xp,
                                                  float* __restrict__ hs,
                                                  uint2* __restrict__ hsp) {
    extern __shared__ float2 sm2[];
    float2* Wsm = sm2;
    float2* Hsm = sm2 + L2_HOFF;
    float*  gt  = (float*)(sm2 + L2_F2);
    float*  hex = gt + 32 * 66;

    const int tid = threadIdx.x;
    const int u0  = blockIdx.x * 8;
    const int lane = tid & 31, warp = tid >> 5;
    const int mw = warp >> 2, nw = warp & 3;
    const int gi = lane >> 2, t = lane & 3;

    // ---- load & split Whh slice: m = g*8+u -> global row g*512 + u0 + u --------
    #pragma unroll
    for (int i = 0; i < 32; i++) {
        int idx = tid + 256 * i;           // 32 m x 256 kp
        int m = idx >> 8, kp = idx & 255;
        int row = (m >> 3) * Hh + u0 + (m & 7);
        float2 w = *(const float2*)(Whh + (size_t)row * Hh + 2 * kp);
        float h0 = bf16rt(w.x), h1 = bf16rt(w.y);
        unsigned whi = pack_bf16(w.y, w.x);
        unsigned wlo = pack_bf16(w.y - h1, w.x - h0);
        Wsm[m * LP + kp] = make_float2(__uint_as_float(whi), __uint_as_float(wlo));
    }

    float c_reg[2] = {0.0f, 0.0f};

    for (int s = 0; s < Ss; s++) {
        if (s > 0) {   // stage split h_{s-1}: pure uint4 copy, 128KB/CTA
            const uint4* src = (const uint4*)(hsp + (size_t)((s + 1) & 1) * (64 * 256));
            #pragma unroll
            for (int i = 0; i < 32; i++) {
                int u4 = tid + 256 * i;     // 8192 uint4
                int n = u4 >> 7, j = u4 & 127;
                uint4 v = src[n * 128 + j];
                *(uint4*)&Hsm[n * LP + 2 * j] = v;
            }
        }
        __syncthreads();

        if (s > 0) {   // 3-mma split-bf16 GEMM; warp: m-tile mw, n-tiles {nw, nw+4}
            float acc0[4] = {}, acc1[4] = {};
            const int mrow = (mw * 16 + gi) * LP;
            const int nrow0 = (nw * 8 + gi) * LP;
            const int nrow1 = (nw * 8 + 32 + gi) * LP;
            #pragma unroll 8
            for (int kt = 0; kt < 32; kt++) {
                int kp0 = kt * 8 + t;
                float2 a00 = Wsm[mrow + kp0];
                float2 a10 = Wsm[mrow + 8 * LP + kp0];
                float2 a01 = Wsm[mrow + kp0 + 4];
                float2 a11 = Wsm[mrow + 8 * LP + kp0 + 4];
                float2 b00 = Hsm[nrow0 + kp0];
                float2 b01 = Hsm[nrow0 + kp0 + 4];
                float2 b10 = Hsm[nrow1 + kp0];
                float2 b11 = Hsm[nrow1 + kp0 + 4];
                unsigned ah0 = __float_as_uint(a00.x), ah1 = __float_as_uint(a10.x);
                unsigned ah2 = __float_as_uint(a01.x), ah3 = __float_as_uint(a11.x);
                unsigned al0 = __float_as_uint(a00.y), al1 = __float_as_uint(a10.y);
                unsigned al2 = __float_as_uint(a01.y), al3 = __float_as_uint(a11.y);
                {
                    unsigned bh0 = __float_as_uint(b00.x), bh1 = __float_as_uint(b01.x);
                    unsigned bl0 = __float_as_uint(b00.y), bl1 = __float_as_uint(b01.y);
                    mma_bf16(acc0, ah0, ah1, ah2, ah3, bh0, bh1);
                    mma_bf16(acc0, ah0, ah1, ah2, ah3, bl0, bl1);
                    mma_bf16(acc0, al0, al1, al2, al3, bh0, bh1);
                }
                {
                    unsigned bh0 = __float_as_uint(b10.x), bh1 = __float_as_uint(b11.x);
                    unsigned bl0 = __float_as_uint(b10.y), bl1 = __float_as_uint(b11.y);
                    mma_bf16(acc1, ah0, ah1, ah2, ah3, bh0, bh1);
                    mma_bf16(acc1, ah0, ah1, ah2, ah3, bl0, bl1);
                    mma_bf16(acc1, al0, al1, al2, al3, bh0, bh1);
                }
            }
            int r0 = mw * 16 + gi;
            int col0 = nw * 8 + 2 * t;
            *(float2*)&gt[r0 * 66 + col0]            = make_float2(acc0[0], acc0[1]);
            *(float2*)&gt[(r0 + 8) * 66 + col0]      = make_float2(acc0[2], acc0[3]);
            *(float2*)&gt[r0 * 66 + col0 + 32]       = make_float2(acc1[0], acc1[1]);
            *(float2*)&gt[(r0 + 8) * 66 + col0 + 32] = make_float2(acc1[2], acc1[3]);
        }
        __syncthreads();

        // ---- epilogue: 2 (u,n) pairs per thread; c in regs -----------------
        #pragma unroll
        for (int pp = 0; pp < 2; pp++) {
            int p = tid + pp * 256;
            int u = p >> 6, n = p & 63;
            const float* xr = xp + (size_t)s * (G4 * Bb) + (size_t)(u0 + u) * 64 + n;
            float gv[4];
            #pragma unroll
            for (int g = 0; g < 4; g++) {
                float v = xr[(size_t)g * 32768];
                if (s > 0) v += gt[(g * 8 + u) * 66 + n];
                gv[g] = v;
            }
            float ig = 1.0f / (1.0f + expf(-gv[0]));
            float fg = 1.0f / (1.0f + expf(-gv[1]));
            float gg = tanhf(gv[2]);
            float og = 1.0f / (1.0f + expf(-gv[3]));
            float c = (s == 0) ? (ig * gg) : (fg * c_reg[pp] + ig * gg);
            c_reg[pp] = c;
            float hv = og * tanhf(c);
            hs[(size_t)s * 32768 + (size_t)n * Hh + u0 + u] = hv;
            hex[u * 68 + n] = hv;
        }
        __syncthreads();

        // ---- pack split-bf16 h into global buffer (s&1) ---------------------
        {
            int n = tid >> 2, kpl = tid & 3;
            float v0 = hex[(2 * kpl) * 68 + n];
            float v1 = hex[(2 * kpl + 1) * 68 + n];
            float v0h = bf16rt(v0), v1h = bf16rt(v1);
            unsigned whi = pack_bf16(v1, v0);
            unsigned wlo = pack_bf16(v1 - v1h, v0 - v0h);
            hsp[(size_t)(s & 1) * (64 * 256) + n * 256 + (u0 >> 1) + kpl] =
                make_uint2(whi, wlo);
        }
        gbar(gridDim.x);
    }
}

// ---------------- FC head ----------------
__global__ void k_fc1(const float* __restrict__ w, const float* __restrict__ bias) {
    int t = blockIdx.x * 256 + threadIdx.x;
    int j = t >> 6, b = t & 63;
    const float* lr = g_act + (size_t)511 * (Bb * Hh) + (size_t)b * Hh;
    const float* wr = w + (size_t)j * Hh;
    float a = 0.0f;
    for (int k = 0; k < Hh; k += 4) {
        float4 wv = *(const float4*)(wr + k);
        float4 lv = *(const float4*)(lr + k);
        a += wv.x * lv.x + wv.y * lv.y + wv.z * lv.z + wv.w * lv.w;
    }
    a += bias[j];
    g_fc1[b * Hh + j] = fmaxf(a, 0.0f);
}

__global__ void k_fc2(const float* __restrict__ w, const float* __restrict__ bias,
                      float* __restrict__ out) {
    __shared__ float red[128];
    int b = blockIdx.x, tid = threadIdx.x;
    float a = 0.0f;
    for (int j = tid; j < Hh; j += 128) a += g_fc1[b * Hh + j] * w[j];
    red[tid] = a;
    __syncthreads();
    for (int s2 = 64; s2 > 0; s2 >>= 1) {
        if (tid < s2) red[tid] += red[tid + s2];
        __syncthreads();
    }
    if (tid == 0) out[b] = red[0] + bias[0];
}

// ---------------- launch ----------------
extern "C" void kernel_launch(void* const* d_in, const int* in_sizes, int n_in,
                              void* d_out, int out_size) {
    const float* x   = (const float*)d_in[0];
    const float* th  = (const float*)d_in[1];
    const float* ph  = (const float*)d_in[2];
    const float* tn  = (const float*)d_in[3];
    const float* pn  = (const float*)d_in[4];
    const float* Wih = (const float*)d_in[5];
    const float* Whh = (const float*)d_in[6];
    const float* bih = (const float*)d_in[7];
    const float* bhh = (const float*)d_in[8];
    const float* f1w = (const float*)d_in[9];
    const float* f1b = (const float*)d_in[10];
    const float* f2w = (const float*)d_in[11];
    const float* f2b = (const float*)d_in[12];
    float* out = (float*)d_out;

    cudaFuncSetAttribute(k_xproj, cudaFuncAttributeMaxDynamicSharedMemorySize, XSMEM);
    cudaFuncSetAttribute(k_lstm2, cudaFuncAttributeMaxDynamicSharedMemorySize, LSTM2_SMEM);

    float* xp_ptr  = nullptr;
    float* act_ptr = nullptr;
    uint2* hsp_ptr = nullptr;
    cudaGetSymbolAddress((void**)&xp_ptr, g_xp);
    cudaGetSymbolAddress((void**)&act_ptr, g_act);
    cudaGetSymbolAddress((void**)&hsp_ptr, g_hsp);

    k_trig<<<256, 256>>>(th, ph, tn, pn);
    k_quant<<<dim3(512, 8), 256>>>(x);

    for (int l = 0; l < 2; l++) {
        k_xproj<<<dim3(256, 16), 512, XSMEM>>>(Wih + (size_t)l * G4 * Hh,
                                               bih + (size_t)l * G4,
                                               bhh + (size_t)l * G4,
                                               xp_ptr);
        k_lstm2<<<64, 256, LSTM2_SMEM>>>(Whh + (size_t)l * G4 * Hh,
                                         xp_ptr, act_ptr, hsp_ptr);
    }

    k_fc1<<<128, 256>>>(f1w, f1b);
    k_fc2<<<64, 128>>>(f2w, f2b, out);
}

// round 12
// speedup vs baseline: 1.2444x; 1.1452x over previous
#include <cuda_runtime.h>
#include <cuda_bf16.h>
#include <math.h>

#define Hh 512
#define Bb 64
#define Ss 512
#define Ii 128
#define G4 2048
#define NCTA 64

// ---------------- device-global scratch (no allocations allowed) ----------------
__device__ float g_act[Ss * Bb * Hh];   // (S,B,H): quantum out q, then hs per layer
__device__ float g_xp[Ss * G4 * Bb];    // (S, 4H, B) x-projection, transposed for lstm
__device__ float g_cw[Ii * Hh];         // cos(theta+noise), layout (I,H)
__device__ float g_sw[Ii * Hh];         // sin(phi+noise),   layout (I,H)
__device__ float g_fc1[Bb * Hh];
__device__ uint2 g_hsp[2 * 64 * 256];   // double-buffered split-bf16 h: [buf][n][kp]
__device__ unsigned g_flags[NCTA];      // per-CTA progress flags (reset in k_trig)

// ---------------- acquire/release flag ops ----------------
__device__ __forceinline__ void flag_release(unsigned* p, unsigned v) {
    asm volatile("st.release.gpu.global.u32 [%0], %1;" :: "l"(p), "r"(v) : "memory");
}
__device__ __forceinline__ unsigned flag_acquire(const unsigned* p) {
    unsigned v;
    asm volatile("ld.acquire.gpu.global.u32 %0, [%1];" : "=r"(v) : "l"(p) : "memory");
    return v;
}

// ---------------- cp.async 16B ----------------
__device__ __forceinline__ void cpasync16(unsigned dst, const void* src) {
    asm volatile("cp.async.cg.shared.global [%0], [%1], 16;" :: "r"(dst), "l"(src));
}

// ---------------- tf32 helpers (xproj) ----------------
__device__ __forceinline__ unsigned f2tf32(float x) {
    unsigned u;
    asm("cvt.rna.tf32.f32 %0, %1;" : "=r"(u) : "f"(x));
    return u;
}
__device__ __forceinline__ float2 split2(float x) {
    float hi = __uint_as_float(f2tf32(x));
    float lo = __uint_as_float(f2tf32(x - hi));
    return make_float2(hi, lo);
}
__device__ __forceinline__ void mma_tf32(float c[4],
                                         unsigned a0, unsigned a1, unsigned a2, unsigned a3,
                                         unsigned b0, unsigned b1) {
    asm volatile(
        "mma.sync.aligned.m16n8k8.row.col.f32.tf32.tf32.f32 "
        "{%0,%1,%2,%3},{%4,%5,%6,%7},{%8,%9},{%0,%1,%2,%3};\n"
        : "+f"(c[0]), "+f"(c[1]), "+f"(c[2]), "+f"(c[3])
        : "r"(a0), "r"(a1), "r"(a2), "r"(a3), "r"(b0), "r"(b1));
}

// ---------------- bf16 helpers (lstm) ----------------
__device__ __forceinline__ void mma_bf16(float c[4],
                                         unsigned a0, unsigned a1, unsigned a2, unsigned a3,
                                         unsigned b0, unsigned b1) {
    asm volatile(
        "mma.sync.aligned.m16n8k16.row.col.f32.bf16.bf16.f32 "
        "{%0,%1,%2,%3},{%4,%5,%6,%7},{%8,%9},{%0,%1,%2,%3};\n"
        : "+f"(c[0]), "+f"(c[1]), "+f"(c[2]), "+f"(c[3])
        : "r"(a0), "r"(a1), "r"(a2), "r"(a3), "r"(b0), "r"(b1));
}
__device__ __forceinline__ unsigned pack_bf16(float v1_hi, float v0_lo) {
    unsigned w;
    asm("cvt.rn.bf16x2.f32 %0, %1, %2;" : "=r"(w) : "f"(v1_hi), "f"(v0_lo));
    return w;
}
__device__ __forceinline__ float bf16rt(float v) {
    return __bfloat162float(__float2bfloat16(v));
}

// fast activations (__expf: MUFU-based, rel err ~2^-21)
__device__ __forceinline__ float fsig(float x) {
    return __fdividef(1.0f, 1.0f + __expf(-x));
}
__device__ __forceinline__ float ftanh(float x) {
    return 1.0f - __fdividef(2.0f, __expf(2.0f * x) + 1.0f);
}

// ---------------- trig precompute (+ flag reset each launch) ----------------
__global__ void k_trig(const float* __restrict__ th, const float* __restrict__ ph,
                       const float* __restrict__ tn, const float* __restrict__ pn) {
    if (blockIdx.x == 0 && threadIdx.x < NCTA) g_flags[threadIdx.x] = 0u;
    int i = blockIdx.x * 256 + threadIdx.x;
    if (i < Ii * Hh) {
        g_cw[i] = cosf(th[i] + tn[i]);
        g_sw[i] = sinf(ph[i] + pn[i]);
    }
}

// ---------------- quantum layer: q[s][b][h] = sqrt(real^2 + imag^2) -------------
__global__ void __launch_bounds__(256) k_quant(const float* __restrict__ x) {
    __shared__ float As[16][68], Cs[16][68], Sm[16][68];
    int m0 = blockIdx.x * 64, n0 = blockIdx.y * 64;
    int tid = threadIdx.x;
    int tx = tid & 15, ty = tid >> 4;
    float aR[4][4] = {}, aI[4][4] = {};

    for (int kc = 0; kc < Ii; kc += 16) {
        {
            int ml = tid >> 2, k4 = tid & 3;
            float4 v = *(const float4*)(x + (size_t)(m0 + ml) * Ii + kc + k4 * 4);
            As[k4 * 4 + 0][ml] = v.x; As[k4 * 4 + 1][ml] = v.y;
            As[k4 * 4 + 2][ml] = v.z; As[k4 * 4 + 3][ml] = v.w;
        }
        {
            int k = tid >> 4, n4 = tid & 15;
            float4 c = *(const float4*)(g_cw + (size_t)(kc + k) * Hh + n0 + n4 * 4);
            float4 s = *(const float4*)(g_sw + (size_t)(kc + k) * Hh + n0 + n4 * 4);
            *(float4*)&Cs[k][n4 * 4] = c;
            *(float4*)&Sm[k][n4 * 4] = s;
        }
        __syncthreads();
        #pragma unroll
        for (int k = 0; k < 16; k++) {
            float4 a  = *(const float4*)&As[k][ty * 4];
            float4 bc = *(const float4*)&Cs[k][tx * 4];
            float4 bs = *(const float4*)&Sm[k][tx * 4];
            float av[4] = {a.x, a.y, a.z, a.w};
            float cv[4] = {bc.x, bc.y, bc.z, bc.w};
            float sv[4] = {bs.x, bs.y, bs.z, bs.w};
            #pragma unroll
            for (int i = 0; i < 4; i++) {
                #pragma unroll
                for (int j = 0; j < 4; j++) {
                    aR[i][j] += av[i] * cv[j];
                    aI[i][j] += av[i] * sv[j];
                }
            }
        }
        __syncthreads();
    }
    #pragma unroll
    for (int i = 0; i < 4; i++) {
        int m = m0 + ty * 4 + i;
        int b = m >> 9, s = m & 511;
        float4 o;
        o.x = sqrtf(aR[i][0] * aR[i][0] + aI[i][0] * aI[i][0]);
        o.y = sqrtf(aR[i][1] * aR[i][1] + aI[i][1] * aI[i][1]);
        o.z = sqrtf(aR[i][2] * aR[i][2] + aI[i][2] * aI[i][2]);
        o.w = sqrtf(aR[i][3] * aR[i][3] + aI[i][3] * aI[i][3]);
        *(float4*)(g_act + (size_t)s * (Bb * Hh) + (size_t)b * Hh + n0 + tx * 4) = o;
    }
}

// ---------------- x-projection (tensor cores, split tf32 3-mma) -----------------
#define PIT 133
#define XBUF (32 * PIT)
#define XSMEM (2 * XBUF * 8)

__global__ void __launch_bounds__(512, 1) k_xproj(const float* __restrict__ W,
                                                  const float* __restrict__ bi,
                                                  const float* __restrict__ bh,
                                                  float* __restrict__ xpo) {
    extern __shared__ float2 dyn[];
    __shared__ float bsum[128];

    const int tid = threadIdx.x;
    const int m0 = blockIdx.x * 128;
    const int n0 = blockIdx.y * 128;
    const int lane = tid & 31, warp = tid >> 5;
    const int wm0 = (warp & 3) * 32;
    const int wn0 = (warp >> 2) * 32;
    const int g = lane >> 2, t = lane & 3;

    if (tid < 128) bsum[tid] = bi[n0 + tid] + bh[n0 + tid];

    const int srow = tid >> 2;
    const int sks  = (tid & 3) * 4;
    const float* gA = g_act + (size_t)(m0 + srow) * Hh + sks;
    const float* gB = W + (size_t)(n0 + srow) * Hh + sks;

    float4 ra = *(const float4*)(gA);
    float4 rb = *(const float4*)(gB);

    float acc[2][4][4];
    #pragma unroll
    for (int i = 0; i < 2; i++)
        #pragma unroll
        for (int j = 0; j < 4; j++)
            #pragma unroll
            for (int r = 0; r < 4; r++) acc[i][j][r] = 0.0f;

    {
        float av[4] = {ra.x, ra.y, ra.z, ra.w};
        float bv[4] = {rb.x, rb.y, rb.z, rb.w};
        #pragma unroll
        for (int j = 0; j < 4; j++) {
            dyn[(sks + j) * PIT + srow] = split2(av[j]);
            dyn[16 * PIT + (sks + j) * PIT + srow] = split2(bv[j]);
        }
    }
    __syncthreads();

    for (int it = 0; it < 32; ++it) {
        const float2* Ab = dyn + (it & 1) * XBUF;
        const float2* Bbuf = Ab + 16 * PIT;

        if (it < 31) {
            gA += 16; gB += 16;
            ra = *(const float4*)(gA);
            rb = *(const float4*)(gB);
        }

        #pragma unroll
        for (int ko = 0; ko < 16; ko += 8) {
            float2 Af[2][4];
            #pragma unroll
            for (int mt = 0; mt < 2; mt++) {
                int r0 = wm0 + mt * 16 + g;
                Af[mt][0] = Ab[(ko + t) * PIT + r0];
                Af[mt][1] = Ab[(ko + t) * PIT + r0 + 8];
                Af[mt][2] = Ab[(ko + t + 4) * PIT + r0];
                Af[mt][3] = Ab[(ko + t + 4) * PIT + r0 + 8];
            }
            float2 Bf[4][2];
            #pragma unroll
            for (int nt = 0; nt < 4; nt++) {
                int n = wn0 + nt * 8 + g;
                Bf[nt][0] = Bbuf[(ko + t) * PIT + n];
                Bf[nt][1] = Bbuf[(ko + t + 4) * PIT + n];
            }
            #pragma unroll
            for (int mt = 0; mt < 2; mt++) {
                unsigned ah0 = __float_as_uint(Af[mt][0].x), ah1 = __float_as_uint(Af[mt][1].x);
                unsigned ah2 = __float_as_uint(Af[mt][2].x), ah3 = __float_as_uint(Af[mt][3].x);
                unsigned al0 = __float_as_uint(Af[mt][0].y), al1 = __float_as_uint(Af[mt][1].y);
                unsigned al2 = __float_as_uint(Af[mt][2].y), al3 = __float_as_uint(Af[mt][3].y);
                #pragma unroll
                for (int nt = 0; nt < 4; nt++) {
                    unsigned bh0 = __float_as_uint(Bf[nt][0].x);
                    unsigned bh1 = __float_as_uint(Bf[nt][1].x);
                    unsigned bl0 = __float_as_uint(Bf[nt][0].y);
                    unsigned bl1 = __float_as_uint(Bf[nt][1].y);
                    mma_tf32(acc[mt][nt], ah0, ah1, ah2, ah3, bh0, bh1);
                    mma_tf32(acc[mt][nt], ah0, ah1, ah2, ah3, bl0, bl1);
                    mma_tf32(acc[mt][nt], al0, al1, al2, al3, bh0, bh1);
                }
            }
        }

        if (it < 31) {
            float2* An = dyn + ((it + 1) & 1) * XBUF;
            float av[4] = {ra.x, ra.y, ra.z, ra.w};
            float bv[4] = {rb.x, rb.y, rb.z, rb.w};
            #pragma unroll
            for (int j = 0; j < 4; j++) {
                An[(sks + j) * PIT + srow] = split2(av[j]);
                An[16 * PIT + (sks + j) * PIT + srow] = split2(bv[j]);
            }
        }
        __syncthreads();
    }

    #pragma unroll
    for (int mt = 0; mt < 2; mt++) {
        int r0g = m0 + wm0 + mt * 16 + g;
        int s0 = r0g >> 6, b0 = r0g & 63;
        int s1 = (r0g + 8) >> 6, b1 = (r0g + 8) & 63;
        #pragma unroll
        for (int nt = 0; nt < 4; nt++) {
            int col = wn0 + nt * 8 + 2 * t;
            float bs0 = bsum[col], bs1 = bsum[col + 1];
            size_t i00 = (size_t)s0 * 131072 + (size_t)(n0 + col) * 64 + b0;
            size_t i10 = (size_t)s1 * 131072 + (size_t)(n0 + col) * 64 + b1;
            xpo[i00]      = acc[mt][nt][0] + bs0;
            xpo[i00 + 64] = acc[mt][nt][1] + bs1;
            xpo[i10]      = acc[mt][nt][2] + bs0;
            xpo[i10 + 64] = acc[mt][nt][3] + bs1;
        }
    }
}

// ---------------- persistent LSTM recurrence, split-bf16 tensor cores -----------
// 64 CTAs x 256 thr. CTA owns 8 hidden units -> 32 gate rows m = g*8+u.
// Per step: C[32,64] = W[32,512].h[512,64] via 3-mma split bf16, fp32 acc.
// Barrier: per-CTA release flags + acquire polling (no membar, no atomics).
#define LP 258
#define L2_HOFF (32 * LP)
#define L2_F2   (L2_HOFF + 64 * LP)
#define LSTM2_SMEM (L2_F2 * 8 + 32 * 66 * 4)

__global__ void __launch_bounds__(256, 1) k_lstm2(const float* __restrict__ Whh,
                                                  const float* __restrict__ xp,
                                                  float* __restrict__ hs,
                                                  uint2* __restrict__ hsp,
                                                  int base) {
    extern __shared__ float2 sm2[];
    float2* Wsm = sm2;
    float2* Hsm = sm2 + L2_HOFF;
    float*  gt  = (float*)(sm2 + L2_F2);

    const int tid = threadIdx.x;
    const int cta = blockIdx.x;
    const int u0  = cta * 8;
    const int lane = tid & 31, warp = tid >> 5;
    const int mw = warp >> 2, nw = warp & 3;
    const int gi = lane >> 2, t = lane & 3;
    const unsigned hsm_u32 = (unsigned)__cvta_generic_to_shared(Hsm);

    // ---- load & split Whh slice ----
    #pragma unroll
    for (int i = 0; i < 32; i++) {
        int idx = tid + 256 * i;
        int m = idx >> 8, kp = idx & 255;
        int row = (m >> 3) * Hh + u0 + (m & 7);
        float2 w = *(const float2*)(Whh + (size_t)row * Hh + 2 * kp);
        float h0 = bf16rt(w.x), h1 = bf16rt(w.y);
        unsigned whi = pack_bf16(w.y, w.x);
        unsigned wlo = pack_bf16(w.y - h1, w.x - h0);
        Wsm[m * LP + kp] = make_float2(__uint_as_float(whi), __uint_as_float(wlo));
    }
    __syncthreads();

    // epilogue mapping: n = batch, up = unit-pair (units 2up, 2up+1)
    const int en = tid & 63;
    const int up = tid >> 6;        // 0..3
    float c0 = 0.0f, c1 = 0.0f;

    for (int s = 0; s < Ss; s++) {
        // ---- prefetch xp gates for this step (independent of h) ----
        float xv[8];
        {
            const float* xr = xp + (size_t)s * (G4 * Bb) + (size_t)(u0 + 2 * up) * 64 + en;
            #pragma unroll
            for (int g = 0; g < 4; g++) {
                xv[g]     = xr[(size_t)g * 32768];
                xv[4 + g] = xr[(size_t)g * 32768 + 64];
            }
        }

        if (s > 0) {
            // ---- wait for all CTAs to publish h(s-1) ----
            if (tid < NCTA) {
                unsigned target = (unsigned)(base + s);
                while (flag_acquire(&g_flags[tid]) < target) {}
            }
            __syncthreads();

            // ---- stage split h via cp.async (no data registers) ----
            const uint2* src = hsp + (size_t)((s + 1) & 1) * (64 * 256);
            #pragma unroll
            for (int i = 0; i < 32; i++) {
                int u4 = tid + 256 * i;
                int n = u4 >> 7, j = u4 & 127;
                cpasync16(hsm_u32 + (unsigned)((n * LP + 2 * j) * 8),
                          src + n * 256 + j * 2);
            }
            asm volatile("cp.async.commit_group;\n\tcp.async.wait_group 0;" ::: "memory");
            __syncthreads();

            // ---- 3-mma split-bf16 GEMM ----
            float acc0[4] = {}, acc1[4] = {};
            const int mrow = (mw * 16 + gi) * LP;
            const int nrow0 = (nw * 8 + gi) * LP;
            const int nrow1 = (nw * 8 + 32 + gi) * LP;
            #pragma unroll 8
            for (int kt = 0; kt < 32; kt++) {
                int kp0 = kt * 8 + t;
                float2 a00 = Wsm[mrow + kp0];
                float2 a10 = Wsm[mrow + 8 * LP + kp0];
                float2 a01 = Wsm[mrow + kp0 + 4];
                float2 a11 = Wsm[mrow + 8 * LP + kp0 + 4];
                float2 b00 = Hsm[nrow0 + kp0];
                float2 b01 = Hsm[nrow0 + kp0 + 4];
                float2 b10 = Hsm[nrow1 + kp0];
                float2 b11 = Hsm[nrow1 + kp0 + 4];
                unsigned ah0 = __float_as_uint(a00.x), ah1 = __float_as_uint(a10.x);
                unsigned ah2 = __float_as_uint(a01.x), ah3 = __float_as_uint(a11.x);
                unsigned al0 = __float_as_uint(a00.y), al1 = __float_as_uint(a10.y);
                unsigned al2 = __float_as_uint(a01.y), al3 = __float_as_uint(a11.y);
                {
                    unsigned bh0 = __float_as_uint(b00.x), bh1 = __float_as_uint(b01.x);
                    unsigned bl0 = __float_as_uint(b00.y), bl1 = __float_as_uint(b01.y);
                    mma_bf16(acc0, ah0, ah1, ah2, ah3, bh0, bh1);
                    mma_bf16(acc0, ah0, ah1, ah2, ah3, bl0, bl1);
                    mma_bf16(acc0, al0, al1, al2, al3, bh0, bh1);
                }
                {
                    unsigned bh0 = __float_as_uint(b10.x), bh1 = __float_as_uint(b11.x);
                    unsigned bl0 = __float_as_uint(b10.y), bl1 = __float_as_uint(b11.y);
                    mma_bf16(acc1, ah0, ah1, ah2, ah3, bh0, bh1);
                    mma_bf16(acc1, ah0, ah1, ah2, ah3, bl0, bl1);
                    mma_bf16(acc1, al0, al1, al2, al3, bh0, bh1);
                }
            }
            int r0 = mw * 16 + gi;
            int col0 = nw * 8 + 2 * t;
            *(float2*)&gt[r0 * 66 + col0]            = make_float2(acc0[0], acc0[1]);
            *(float2*)&gt[(r0 + 8) * 66 + col0]      = make_float2(acc0[2], acc0[3]);
            *(float2*)&gt[r0 * 66 + col0 + 32]       = make_float2(acc1[0], acc1[1]);
            *(float2*)&gt[(r0 + 8) * 66 + col0 + 32] = make_float2(acc1[2], acc1[3]);
            __syncthreads();
        }

        // ---- fused epilogue + pack: thread owns units (2up, 2up+1), batch en ----
        {
            float g0[4], g1[4];
            #pragma unroll
            for (int g = 0; g < 4; g++) {
                float v0 = xv[g], v1 = xv[4 + g];
                if (s > 0) {
                    v0 += gt[(g * 8 + 2 * up) * 66 + en];
                    v1 += gt[(g * 8 + 2 * up + 1) * 66 + en];
                }
                g0[g] = v0; g1[g] = v1;
            }
            float i0 = fsig(g0[0]), f0 = fsig(g0[1]), gg0 = ftanh(g0[2]), o0 = fsig(g0[3]);
            float i1 = fsig(g1[0]), f1 = fsig(g1[1]), gg1 = ftanh(g1[2]), o1 = fsig(g1[3]);
            c0 = (s == 0) ? (i0 * gg0) : (f0 * c0 + i0 * gg0);
            c1 = (s == 0) ? (i1 * gg1) : (f1 * c1 + i1 * gg1);
            float h0 = o0 * ftanh(c0);
            float h1 = o1 * ftanh(c1);
            *(float2*)&hs[(size_t)s * 32768 + (size_t)en * Hh + u0 + 2 * up] =
                make_float2(h0, h1);
            float h0r = bf16rt(h0), h1r = bf16rt(h1);
            unsigned whi = pack_bf16(h1, h0);
            unsigned wlo = pack_bf16(h1 - h1r, h0 - h0r);
            hsp[(size_t)(s & 1) * (64 * 256) + en * 256 + (u0 >> 1) + up] =
                make_uint2(whi, wlo);
        }
        __syncthreads();
        if (tid == 0) flag_release(&g_flags[cta], (unsigned)(base + s + 1));
    }
}

// ---------------- FC head ----------------
__global__ void k_fc1(const float* __restrict__ w, const float* __restrict__ bias) {
    int t = blockIdx.x * 256 + threadIdx.x;
    int j = t >> 6, b = t & 63;
    const float* lr = g_act + (size_t)511 * (Bb * Hh) + (size_t)b * Hh;
    const float* wr = w + (size_t)j * Hh;
    float a = 0.0f;
    for (int k = 0; k < Hh; k += 4) {
        float4 wv = *(const float4*)(wr + k);
        float4 lv = *(const float4*)(lr + k);
        a += wv.x * lv.x + wv.y * lv.y + wv.z * lv.z + wv.w * lv.w;
    }
    a += bias[j];
    g_fc1[b * Hh + j] = fmaxf(a, 0.0f);
}

__global__ void k_fc2(const float* __restrict__ w, const float* __restrict__ bias,
                      float* __restrict__ out) {
    __shared__ float red[128];
    int b = blockIdx.x, tid = threadIdx.x;
    float a = 0.0f;
    for (int j = tid; j < Hh; j += 128) a += g_fc1[b * Hh + j] * w[j];
    red[tid] = a;
    __syncthreads();
    for (int s2 = 64; s2 > 0; s2 >>= 1) {
        if (tid < s2) red[tid] += red[tid + s2];
        __syncthreads();
    }
    if (tid == 0) out[b] = red[0] + bias[0];
}

// ---------------- launch ----------------
extern "C" void kernel_launch(void* const* d_in, const int* in_sizes, int n_in,
                              void* d_out, int out_size) {
    const float* x   = (const float*)d_in[0];
    const float* th  = (const float*)d_in[1];
    const float* ph  = (const float*)d_in[2];
    const float* tn  = (const float*)d_in[3];
    const float* pn  = (const float*)d_in[4];
    const float* Wih = (const float*)d_in[5];
    const float* Whh = (const float*)d_in[6];
    const float* bih = (const float*)d_in[7];
    const float* bhh = (const float*)d_in[8];
    const float* f1w = (const float*)d_in[9];
    const float* f1b = (const float*)d_in[10];
    const float* f2w = (const float*)d_in[11];
    const float* f2b = (const float*)d_in[12];
    float* out = (float*)d_out;

    cudaFuncSetAttribute(k_xproj, cudaFuncAttributeMaxDynamicSharedMemorySize, XSMEM);
    cudaFuncSetAttribute(k_lstm2, cudaFuncAttributeMaxDynamicSharedMemorySize, LSTM2_SMEM);

    float* xp_ptr  = nullptr;
    float* act_ptr = nullptr;
    uint2* hsp_ptr = nullptr;
    cudaGetSymbolAddress((void**)&xp_ptr, g_xp);
    cudaGetSymbolAddress((void**)&act_ptr, g_act);
    cudaGetSymbolAddress((void**)&hsp_ptr, g_hsp);

    k_trig<<<256, 256>>>(th, ph, tn, pn);
    k_quant<<<dim3(512, 8), 256>>>(x);

    for (int l = 0; l < 2; l++) {
        k_xproj<<<dim3(256, 16), 512, XSMEM>>>(Wih + (size_t)l * G4 * Hh,
                                               bih + (size_t)l * G4,
                                               bhh + (size_t)l * G4,
                                               xp_ptr);
        k_lstm2<<<NCTA, 256, LSTM2_SMEM>>>(Whh + (size_t)l * G4 * Hh,
                                           xp_ptr, act_ptr, hsp_ptr, l * Ss);
    }

    k_fc1<<<128, 256>>>(f1w, f1b);
    k_fc2<<<64, 128>>>(f2w, f2b, out);
}